// round 7
// baseline (speedup 1.0000x reference)
#include <cuda_runtime.h>
#include <cuda_bf16.h>
#include <cstdint>

#define BATCH 4
#define SEQ   2048
#define NHEAD 16
#define HDIM  64
#define HID   1024
#define NEG_F (-3.4028234663852886e38f)

// Scratch: Q/K/V in [b*NH + h][s][d] layout (fp32), device globals.
__device__ float g_q[BATCH * NHEAD * SEQ * HDIM];
__device__ float g_k[BATCH * NHEAD * SEQ * HDIM];
__device__ float g_v[BATCH * NHEAD * SEQ * HDIM];

__device__ __forceinline__ float neg_inf_f() { return __int_as_float(0xff800000); }

__device__ __forceinline__ void mma16816(float* d, const uint32_t* a, const uint32_t* b) {
    asm volatile(
        "mma.sync.aligned.m16n8k16.row.col.f32.bf16.bf16.f32 "
        "{%0,%1,%2,%3}, {%4,%5,%6,%7}, {%8,%9}, {%0,%1,%2,%3};"
        : "+f"(d[0]), "+f"(d[1]), "+f"(d[2]), "+f"(d[3])
        : "r"(a[0]), "r"(a[1]), "r"(a[2]), "r"(a[3]), "r"(b[0]), "r"(b[1]));
}

__device__ __forceinline__ void split_bf16(float f, __nv_bfloat16& h, __nv_bfloat16& l) {
    h = __float2bfloat16(f);
    l = __float2bfloat16(f - __bfloat162float(h));
}

// ---------------------------------------------------------------------------
// Kernel 1: Y = X @ W + b via bf16x3-split tensor-core MMA (hh + hl + lh).
// BM=128, BN=128, BK=32. 256 threads = 8 warps in 2(m) x 4(n); warp tile
// 64m x 32n = 4x4 m16n8k16 fragments. Smem rows padded to 40 bf16 (80B):
// fragment-load banks (r*20+t) mod 32 are all distinct -> conflict-free.
// Output written into [bh][s][d] scratch layout with bias.
// ---------------------------------------------------------------------------
__global__ __launch_bounds__(256) void qkv_kernel(
    const float* __restrict__ X,
    const float* __restrict__ Wq, const float* __restrict__ Bq,
    const float* __restrict__ Wk, const float* __restrict__ Bk,
    const float* __restrict__ Wv, const float* __restrict__ Bv)
{
    const int z = blockIdx.z;
    const float* __restrict__ W  = (z == 0) ? Wq : (z == 1) ? Wk : Wv;
    const float* __restrict__ Bi = (z == 0) ? Bq : (z == 1) ? Bk : Bv;
    float* __restrict__ dst      = (z == 0) ? g_q : (z == 1) ? g_k : g_v;

    __shared__ __nv_bfloat16 Xh[128 * 40];  // X tile [m][k] hi
    __shared__ __nv_bfloat16 Xl[128 * 40];  // X tile [m][k] lo
    __shared__ __nv_bfloat16 Wh[128 * 40];  // W tile [n][k] hi (transposed)
    __shared__ __nv_bfloat16 Wl[128 * 40];  // W tile [n][k] lo

    const int tid  = threadIdx.x;
    const int warp = tid >> 5;
    const int lane = tid & 31;
    const int g    = lane >> 2;      // fragment group row/col
    const int t    = lane & 3;       // fragment k pair index
    const int wm   = (warp >> 2) * 64;
    const int wn   = (warp & 3) * 32;
    const int m0   = blockIdx.y * 128;
    const int n0   = blockIdx.x * 128;

    float D[4][4][4];
#pragma unroll
    for (int fi = 0; fi < 4; fi++)
#pragma unroll
        for (int fj = 0; fj < 4; fj++)
#pragma unroll
            for (int e = 0; e < 4; e++) D[fi][fj][e] = 0.f;

    for (int k0 = 0; k0 < HID; k0 += 32) {
        // Stage X tile (128 x 32): 1024 float4s, 4 per thread. Split hi/lo.
#pragma unroll
        for (int p = 0; p < 4; p++) {
            int i  = tid + p * 256;
            int m  = i >> 3;
            int kq = i & 7;
            float4 v = *(const float4*)(X + (size_t)(m0 + m) * HID + k0 + kq * 4);
            const float f[4] = {v.x, v.y, v.z, v.w};
#pragma unroll
            for (int j = 0; j < 4; j++) {
                __nv_bfloat16 h, l;
                split_bf16(f[j], h, l);
                Xh[m * 40 + kq * 4 + j] = h;
                Xl[m * 40 + kq * 4 + j] = l;
            }
        }
        // Stage W tile (32 x 128) transposed to [n][k]: 1024 float4s.
#pragma unroll
        for (int p = 0; p < 4; p++) {
            int i  = tid + p * 256;
            int kr = i >> 5;
            int nq = i & 31;
            float4 v = *(const float4*)(W + (size_t)(k0 + kr) * HID + n0 + nq * 4);
            const float f[4] = {v.x, v.y, v.z, v.w};
#pragma unroll
            for (int j = 0; j < 4; j++) {
                __nv_bfloat16 h, l;
                split_bf16(f[j], h, l);
                Wh[(nq * 4 + j) * 40 + kr] = h;
                Wl[(nq * 4 + j) * 40 + kr] = l;
            }
        }
        __syncthreads();

#pragma unroll
        for (int ks = 0; ks < 2; ks++) {
            const int kb = ks * 16 + 2 * t;
            uint32_t Ah[4][4], Al[4][4];
#pragma unroll
            for (int fi = 0; fi < 4; fi++) {
                int r = wm + fi * 16 + g;
                Ah[fi][0] = *(const uint32_t*)&Xh[r * 40 + kb];
                Ah[fi][1] = *(const uint32_t*)&Xh[(r + 8) * 40 + kb];
                Ah[fi][2] = *(const uint32_t*)&Xh[r * 40 + kb + 8];
                Ah[fi][3] = *(const uint32_t*)&Xh[(r + 8) * 40 + kb + 8];
                Al[fi][0] = *(const uint32_t*)&Xl[r * 40 + kb];
                Al[fi][1] = *(const uint32_t*)&Xl[(r + 8) * 40 + kb];
                Al[fi][2] = *(const uint32_t*)&Xl[r * 40 + kb + 8];
                Al[fi][3] = *(const uint32_t*)&Xl[(r + 8) * 40 + kb + 8];
            }
            uint32_t Bh[4][2], Bl[4][2];
#pragma unroll
            for (int fj = 0; fj < 4; fj++) {
                int c = wn + fj * 8 + g;
                Bh[fj][0] = *(const uint32_t*)&Wh[c * 40 + kb];
                Bh[fj][1] = *(const uint32_t*)&Wh[c * 40 + kb + 8];
                Bl[fj][0] = *(const uint32_t*)&Wl[c * 40 + kb];
                Bl[fj][1] = *(const uint32_t*)&Wl[c * 40 + kb + 8];
            }
#pragma unroll
            for (int fi = 0; fi < 4; fi++)
#pragma unroll
                for (int fj = 0; fj < 4; fj++) {
                    mma16816(D[fi][fj], Ah[fi], Bh[fj]);   // hi*hi
                    mma16816(D[fi][fj], Ah[fi], Bl[fj]);   // hi*lo
                    mma16816(D[fi][fj], Al[fi], Bh[fj]);   // lo*hi
                }
        }
        __syncthreads();
    }

    // Epilogue: D[fi][fj] rows = wm+fi*16+g (+8), cols = wn+fj*8+2t (+1).
#pragma unroll
    for (int fj = 0; fj < 4; fj++) {
        const int ncol = n0 + wn + fj * 8 + 2 * t;
        const int h    = ncol >> 6;
        const int d0c  = ncol & 63;
        const float b0 = Bi[ncol];
        const float b1 = Bi[ncol + 1];
#pragma unroll
        for (int fi = 0; fi < 4; fi++) {
#pragma unroll
            for (int half = 0; half < 2; half++) {
                int m  = m0 + wm + fi * 16 + g + half * 8;
                int bi = m >> 11;
                int s  = m & (SEQ - 1);
                float2 o;
                o.x = D[fi][fj][half * 2 + 0] + b0;
                o.y = D[fi][fj][half * 2 + 1] + b1;
                *(float2*)(dst + ((size_t)(bi * NHEAD + h) * SEQ + s) * HDIM + d0c) = o;
            }
        }
    }
}

// ---------------------------------------------------------------------------
// Kernel 2: flash attention, BQ=128 x BK=128 tiles, 256 threads. (unchanged)
// ---------------------------------------------------------------------------
__global__ __launch_bounds__(256) void attn_kernel(
    const int* __restrict__ mask,
    float* __restrict__ out)
{
    extern __shared__ float sm[];
    float* QsT = sm;            // [d][q]  64x128
    float* UN  = sm + 8192;     // KT [d][k] 64x128, then P [q][k] 128x128
    float* Vs  = sm + 24576;    // [k][d] 128x64

    const int tid = threadIdx.x;
    const int tx  = tid & 15;
    const int ty  = tid >> 4;
    const int r0  = ty * 8;
    const int cA  = tx * 4;
    const int cB  = 64 + tx * 4;
    const int q0  = blockIdx.x * 128;
    const int bh  = blockIdx.y;
    const int b   = bh >> 4;
    const int h   = bh & 15;

    const float* __restrict__ Q = g_q + (size_t)bh * SEQ * HDIM;
    const float* __restrict__ K = g_k + (size_t)bh * SEQ * HDIM;
    const float* __restrict__ V = g_v + (size_t)bh * SEQ * HDIM;
    const int* __restrict__ mrow = mask + (size_t)b * SEQ;

#pragma unroll
    for (int p = 0; p < 8; p++) {
        int idx = tid + p * 256;
        int ql  = idx & 127;
        int dq  = idx >> 7;
        float4 v = *(const float4*)(Q + (size_t)(q0 + ql) * HDIM + dq * 4);
        QsT[(dq * 4 + 0) * 128 + ql] = v.x;
        QsT[(dq * 4 + 1) * 128 + ql] = v.y;
        QsT[(dq * 4 + 2) * 128 + ql] = v.z;
        QsT[(dq * 4 + 3) * 128 + ql] = v.w;
    }

    float acc[8][4];
    float mprev[8], lsum[8];
#pragma unroll
    for (int i = 0; i < 8; i++) {
        mprev[i] = neg_inf_f();
        lsum[i]  = 0.f;
#pragma unroll
        for (int j = 0; j < 4; j++) acc[i][j] = 0.f;
    }

    for (int kt = 0; kt < SEQ / 128; kt++) {
        const int k0 = kt * 128;
        __syncthreads();

#pragma unroll
        for (int p = 0; p < 8; p++) {
            int idx = tid + p * 256;
            int kl = idx & 127, dq = idx >> 7;
            float4 v = *(const float4*)(K + (size_t)(k0 + kl) * HDIM + dq * 4);
            UN[(dq * 4 + 0) * 128 + kl] = v.x;
            UN[(dq * 4 + 1) * 128 + kl] = v.y;
            UN[(dq * 4 + 2) * 128 + kl] = v.z;
            UN[(dq * 4 + 3) * 128 + kl] = v.w;
            int vl = idx >> 4, dv = idx & 15;
            float4 w = *(const float4*)(V + (size_t)(k0 + vl) * HDIM + dv * 4);
            *(float4*)&Vs[vl * 64 + dv * 4] = w;
        }
        __syncthreads();

        float s[8][8];
#pragma unroll
        for (int i = 0; i < 8; i++)
#pragma unroll
            for (int j = 0; j < 8; j++) s[i][j] = 0.f;

#pragma unroll 4
        for (int d = 0; d < HDIM; d++) {
            float4 a0 = *(const float4*)&QsT[d * 128 + r0];
            float4 a1 = *(const float4*)&QsT[d * 128 + r0 + 4];
            float4 b0 = *(const float4*)&UN[d * 128 + cA];
            float4 b1 = *(const float4*)&UN[d * 128 + cB];
            float a[8] = {a0.x, a0.y, a0.z, a0.w, a1.x, a1.y, a1.z, a1.w};
            float bb[8] = {b0.x, b0.y, b0.z, b0.w, b1.x, b1.y, b1.z, b1.w};
#pragma unroll
            for (int i = 0; i < 8; i++)
#pragma unroll
                for (int j = 0; j < 8; j++)
                    s[i][j] = fmaf(a[i], bb[j], s[i][j]);
        }

        float bias[8];
#pragma unroll
        for (int j = 0; j < 4; j++) {
            bias[j]     = (mrow[k0 + cA + j] != 0) ? 0.f : NEG_F;
            bias[4 + j] = (mrow[k0 + cB + j] != 0) ? 0.f : NEG_F;
        }

#pragma unroll
        for (int i = 0; i < 8; i++) {
            float mx = neg_inf_f();
#pragma unroll
            for (int j = 0; j < 8; j++) {
                s[i][j] = fmaf(s[i][j], 0.125f, bias[j]);
                mx = fmaxf(mx, s[i][j]);
            }
            mx = fmaxf(mx, __shfl_xor_sync(0xffffffffu, mx, 8));
            mx = fmaxf(mx, __shfl_xor_sync(0xffffffffu, mx, 4));
            mx = fmaxf(mx, __shfl_xor_sync(0xffffffffu, mx, 2));
            mx = fmaxf(mx, __shfl_xor_sync(0xffffffffu, mx, 1));
            float mnew = fmaxf(mprev[i], mx);
            float sf   = __expf(mprev[i] - mnew);
            float rs   = 0.f;
#pragma unroll
            for (int j = 0; j < 8; j++) {
                s[i][j] = __expf(s[i][j] - mnew);
                rs += s[i][j];
            }
            rs += __shfl_xor_sync(0xffffffffu, rs, 8);
            rs += __shfl_xor_sync(0xffffffffu, rs, 4);
            rs += __shfl_xor_sync(0xffffffffu, rs, 2);
            rs += __shfl_xor_sync(0xffffffffu, rs, 1);
            lsum[i]  = lsum[i] * sf + rs;
            mprev[i] = mnew;
#pragma unroll
            for (int j = 0; j < 4; j++) acc[i][j] *= sf;
        }
        __syncthreads();

#pragma unroll
        for (int i = 0; i < 8; i++) {
            *(float4*)&UN[(r0 + i) * 128 + cA] =
                make_float4(s[i][0], s[i][1], s[i][2], s[i][3]);
            *(float4*)&UN[(r0 + i) * 128 + cB] =
                make_float4(s[i][4], s[i][5], s[i][6], s[i][7]);
        }
        __syncthreads();

#pragma unroll 2
        for (int k4 = 0; k4 < 32; k4++) {
            float4 v0 = *(const float4*)&Vs[(k4 * 4 + 0) * 64 + tx * 4];
            float4 v1 = *(const float4*)&Vs[(k4 * 4 + 1) * 64 + tx * 4];
            float4 v2 = *(const float4*)&Vs[(k4 * 4 + 2) * 64 + tx * 4];
            float4 v3 = *(const float4*)&Vs[(k4 * 4 + 3) * 64 + tx * 4];
            float bv[4][4] = {{v0.x, v0.y, v0.z, v0.w},
                              {v1.x, v1.y, v1.z, v1.w},
                              {v2.x, v2.y, v2.z, v2.w},
                              {v3.x, v3.y, v3.z, v3.w}};
#pragma unroll
            for (int i = 0; i < 8; i++) {
                float4 a4 = *(const float4*)&UN[(r0 + i) * 128 + k4 * 4];
                float aa[4] = {a4.x, a4.y, a4.z, a4.w};
#pragma unroll
                for (int c = 0; c < 4; c++)
#pragma unroll
                    for (int jj = 0; jj < 4; jj++)
                        acc[i][c] = fmaf(aa[jj], bv[jj][c], acc[i][c]);
            }
        }
    }

#pragma unroll
    for (int i = 0; i < 8; i++) {
        float inv = 1.0f / lsum[i];
        float4 o = make_float4(acc[i][0] * inv, acc[i][1] * inv,
                               acc[i][2] * inv, acc[i][3] * inv);
        int srow = q0 + r0 + i;
        *(float4*)(out + ((size_t)(b * SEQ + srow)) * HID + h * HDIM + tx * 4) = o;
    }
}

extern "C" void kernel_launch(void* const* d_in, const int* in_sizes, int n_in,
                              void* d_out, int out_size) {
    const float* X    = (const float*)d_in[0];
    const int*   mask = (const int*)d_in[1];
    const float* Wq   = (const float*)d_in[2];
    const float* Bq   = (const float*)d_in[3];
    const float* Wk   = (const float*)d_in[4];
    const float* Bk   = (const float*)d_in[5];
    const float* Wv   = (const float*)d_in[6];
    const float* Bv   = (const float*)d_in[7];
    float* out = (float*)d_out;

    dim3 g1(HID / 128, (BATCH * SEQ) / 128, 3);
    qkv_kernel<<<g1, 256>>>(X, Wq, Bq, Wk, Bk, Wv, Bv);

    static const int smem_bytes = 128 * 1024;
    cudaFuncSetAttribute(attn_kernel,
                         cudaFuncAttributeMaxDynamicSharedMemorySize, smem_bytes);
    dim3 g2(SEQ / 128, BATCH * NHEAD);
    attn_kernel<<<g2, 256, smem_bytes>>>(mask, out);
}

// round 8
// speedup vs baseline: 1.0935x; 1.0935x over previous
#include <cuda_runtime.h>

#define BATCH 4
#define SEQ   2048
#define NHEAD 16
#define HDIM  64
#define HID   1024
#define NEG_F (-3.4028234663852886e38f)

// Scratch: Q/K/V in [b*NH + h][s][d] layout (fp32), device globals.
__device__ float g_q[BATCH * NHEAD * SEQ * HDIM];
__device__ float g_k[BATCH * NHEAD * SEQ * HDIM];
__device__ float g_v[BATCH * NHEAD * SEQ * HDIM];

__device__ __forceinline__ float neg_inf_f() { return __int_as_float(0xff800000); }

// ---------------------------------------------------------------------------
// Kernel 1: Y = X @ W + b for W in {Wq,Wk,Wv} (blockIdx.z selects).
// BM=128, BN=128, BK=16, 256 threads, 8x8 micro. (round-6 proven: ~1127us)
// ---------------------------------------------------------------------------
__global__ __launch_bounds__(256) void qkv_kernel(
    const float* __restrict__ X,
    const float* __restrict__ Wq, const float* __restrict__ Bq,
    const float* __restrict__ Wk, const float* __restrict__ Bk,
    const float* __restrict__ Wv, const float* __restrict__ Bv)
{
    const int z = blockIdx.z;
    const float* __restrict__ W  = (z == 0) ? Wq : (z == 1) ? Wk : Wv;
    const float* __restrict__ Bi = (z == 0) ? Bq : (z == 1) ? Bk : Bv;
    float* __restrict__ dst      = (z == 0) ? g_q : (z == 1) ? g_k : g_v;

    __shared__ float XsT[16][132];
    __shared__ float Ws[16][128];

    const int tid = threadIdx.x;
    const int tx  = tid & 15;
    const int ty  = tid >> 4;
    const int m0  = blockIdx.y * 128;
    const int n0  = blockIdx.x * 128;

    float acc[8][8];
#pragma unroll
    for (int i = 0; i < 8; i++)
#pragma unroll
        for (int j = 0; j < 8; j++) acc[i][j] = 0.f;

    for (int k0 = 0; k0 < HID; k0 += 16) {
#pragma unroll
        for (int p = 0; p < 2; p++) {
            int i  = tid + p * 256;
            int ml = i >> 2;
            int kq = i & 3;
            float4 v = *(const float4*)(X + (size_t)(m0 + ml) * HID + k0 + kq * 4);
            XsT[kq * 4 + 0][ml] = v.x;
            XsT[kq * 4 + 1][ml] = v.y;
            XsT[kq * 4 + 2][ml] = v.z;
            XsT[kq * 4 + 3][ml] = v.w;
        }
#pragma unroll
        for (int p = 0; p < 2; p++) {
            int i  = tid + p * 256;
            int kr = i >> 5;
            int nq = i & 31;
            float4 v = *(const float4*)(W + (size_t)(k0 + kr) * HID + n0 + nq * 4);
            *(float4*)&Ws[kr][nq * 4] = v;
        }
        __syncthreads();
#pragma unroll
        for (int kk = 0; kk < 16; kk++) {
            float4 a0 = *(const float4*)&XsT[kk][ty * 8];
            float4 a1 = *(const float4*)&XsT[kk][ty * 8 + 4];
            float4 b0 = *(const float4*)&Ws[kk][tx * 8];
            float4 b1 = *(const float4*)&Ws[kk][tx * 8 + 4];
            float a[8] = {a0.x, a0.y, a0.z, a0.w, a1.x, a1.y, a1.z, a1.w};
            float bb[8] = {b0.x, b0.y, b0.z, b0.w, b1.x, b1.y, b1.z, b1.w};
#pragma unroll
            for (int i = 0; i < 8; i++)
#pragma unroll
                for (int j = 0; j < 8; j++)
                    acc[i][j] = fmaf(a[i], bb[j], acc[i][j]);
        }
        __syncthreads();
    }

    const int ncol = n0 + tx * 8;
    const int h    = ncol >> 6;
    const int d0   = ncol & 63;
    float4 bA = *(const float4*)(Bi + ncol);
    float4 bB = *(const float4*)(Bi + ncol + 4);
    const float bb[8] = {bA.x, bA.y, bA.z, bA.w, bB.x, bB.y, bB.z, bB.w};
#pragma unroll
    for (int i = 0; i < 8; i++) {
        int m = m0 + ty * 8 + i;
        int bi = m >> 11;
        int s  = m & (SEQ - 1);
        float* p = dst + ((size_t)(bi * NHEAD + h) * SEQ + s) * HDIM + d0;
        float4 o0, o1;
        o0.x = acc[i][0] + bb[0]; o0.y = acc[i][1] + bb[1];
        o0.z = acc[i][2] + bb[2]; o0.w = acc[i][3] + bb[3];
        o1.x = acc[i][4] + bb[4]; o1.y = acc[i][5] + bb[5];
        o1.z = acc[i][6] + bb[6]; o1.w = acc[i][7] + bb[7];
        *(float4*)(p)     = o0;
        *(float4*)(p + 4) = o1;
    }
}

// ---------------------------------------------------------------------------
// Kernel 2: flash attention, BQ=64 x BK=128 tiles, 128 threads (4 warps).
// Same 8q x 8k S-micro / 8q x 4d PV-micro and same 1.0 B/FMA LDS ratio as the
// round-6 kernel, but 80KB smem -> 2 CTAs/SM (double warps, 128-wide barriers,
// cross-CTA latency hiding). Smem:
//   QsT [64][64]   (d-major Q)                   floats 0..4095     (16KB)
//   UN  [8192]     KT [64][128] then P [64][128] floats 4096..12287 (32KB)
//   Vs  [128][64]                                floats 12288..20479(32KB)
// ---------------------------------------------------------------------------
__global__ __launch_bounds__(128) void attn_kernel(
    const int* __restrict__ mask,
    float* __restrict__ out)
{
    extern __shared__ float sm[];
    float* QsT = sm;             // [d][q]  64x64
    float* UN  = sm + 4096;      // KT [d][k] 64x128, then P [q][k] 64x128
    float* Vs  = sm + 12288;     // [k][d] 128x64

    const int tid = threadIdx.x;
    const int tx  = tid & 15;        // k-col group
    const int ty  = tid >> 4;        // 0..7 query-row group
    const int r0  = ty * 8;          // 8 query rows
    const int cA  = tx * 4;
    const int cB  = 64 + tx * 4;
    const int q0  = blockIdx.x * 64;
    const int bh  = blockIdx.y;
    const int b   = bh >> 4;
    const int h   = bh & 15;

    const float* __restrict__ Q = g_q + (size_t)bh * SEQ * HDIM;
    const float* __restrict__ K = g_k + (size_t)bh * SEQ * HDIM;
    const float* __restrict__ V = g_v + (size_t)bh * SEQ * HDIM;
    const int* __restrict__ mrow = mask + (size_t)b * SEQ;

    // Load Q (64 x 64) transposed: 1024 float4s, 8/thread.
#pragma unroll
    for (int p = 0; p < 8; p++) {
        int idx = tid + p * 128;
        int ql  = idx & 63;
        int dq  = idx >> 6;          // 0..15
        float4 v = *(const float4*)(Q + (size_t)(q0 + ql) * HDIM + dq * 4);
        QsT[(dq * 4 + 0) * 64 + ql] = v.x;
        QsT[(dq * 4 + 1) * 64 + ql] = v.y;
        QsT[(dq * 4 + 2) * 64 + ql] = v.z;
        QsT[(dq * 4 + 3) * 64 + ql] = v.w;
    }

    float acc[8][4];
    float mprev[8], lsum[8];
#pragma unroll
    for (int i = 0; i < 8; i++) {
        mprev[i] = neg_inf_f();
        lsum[i]  = 0.f;
#pragma unroll
        for (int j = 0; j < 4; j++) acc[i][j] = 0.f;
    }

    for (int kt = 0; kt < SEQ / 128; kt++) {
        const int k0 = kt * 128;
        __syncthreads();   // prev-iter P/V reads done; (iter 0) Q visible

        // K (128 x 64) transposed into KT(=UN), V natural into Vs.
        // 2048 float4s each, 16 per thread.
#pragma unroll
        for (int p = 0; p < 16; p++) {
            int idx = tid + p * 128;
            int kl = idx & 127, dq = idx >> 7;     // dq 0..15
            float4 v = *(const float4*)(K + (size_t)(k0 + kl) * HDIM + dq * 4);
            UN[(dq * 4 + 0) * 128 + kl] = v.x;
            UN[(dq * 4 + 1) * 128 + kl] = v.y;
            UN[(dq * 4 + 2) * 128 + kl] = v.z;
            UN[(dq * 4 + 3) * 128 + kl] = v.w;
            int vl = idx >> 4, dv = idx & 15;
            float4 w = *(const float4*)(V + (size_t)(k0 + vl) * HDIM + dv * 4);
            *(float4*)&Vs[vl * 64 + dv * 4] = w;
        }
        __syncthreads();

        // S = Q K^T : 8x8 per thread.
        float s[8][8];
#pragma unroll
        for (int i = 0; i < 8; i++)
#pragma unroll
            for (int j = 0; j < 8; j++) s[i][j] = 0.f;

#pragma unroll 4
        for (int d = 0; d < HDIM; d++) {
            float4 a0 = *(const float4*)&QsT[d * 64 + r0];
            float4 a1 = *(const float4*)&QsT[d * 64 + r0 + 4];
            float4 b0 = *(const float4*)&UN[d * 128 + cA];
            float4 b1 = *(const float4*)&UN[d * 128 + cB];
            float a[8] = {a0.x, a0.y, a0.z, a0.w, a1.x, a1.y, a1.z, a1.w};
            float bb[8] = {b0.x, b0.y, b0.z, b0.w, b1.x, b1.y, b1.z, b1.w};
#pragma unroll
            for (int i = 0; i < 8; i++)
#pragma unroll
                for (int j = 0; j < 8; j++)
                    s[i][j] = fmaf(a[i], bb[j], s[i][j]);
        }

        // Mask bias (select form; inf-proof for 0/1 masks).
        float bias[8];
#pragma unroll
        for (int j = 0; j < 4; j++) {
            bias[j]     = (mrow[k0 + cA + j] != 0) ? 0.f : NEG_F;
            bias[4 + j] = (mrow[k0 + cB + j] != 0) ? 0.f : NEG_F;
        }

        // Online softmax; rows reduce across the 16 tx lanes (xor 8,4,2,1).
#pragma unroll
        for (int i = 0; i < 8; i++) {
            float mx = neg_inf_f();
#pragma unroll
            for (int j = 0; j < 8; j++) {
                s[i][j] = fmaf(s[i][j], 0.125f, bias[j]);   // 1/sqrt(64)
                mx = fmaxf(mx, s[i][j]);
            }
            mx = fmaxf(mx, __shfl_xor_sync(0xffffffffu, mx, 8));
            mx = fmaxf(mx, __shfl_xor_sync(0xffffffffu, mx, 4));
            mx = fmaxf(mx, __shfl_xor_sync(0xffffffffu, mx, 2));
            mx = fmaxf(mx, __shfl_xor_sync(0xffffffffu, mx, 1));
            float mnew = fmaxf(mprev[i], mx);
            float sf   = __expf(mprev[i] - mnew);
            float rs   = 0.f;
#pragma unroll
            for (int j = 0; j < 8; j++) {
                s[i][j] = __expf(s[i][j] - mnew);   // s -> p in place
                rs += s[i][j];
            }
            rs += __shfl_xor_sync(0xffffffffu, rs, 8);
            rs += __shfl_xor_sync(0xffffffffu, rs, 4);
            rs += __shfl_xor_sync(0xffffffffu, rs, 2);
            rs += __shfl_xor_sync(0xffffffffu, rs, 1);
            lsum[i]  = lsum[i] * sf + rs;
            mprev[i] = mnew;
#pragma unroll
            for (int j = 0; j < 4; j++) acc[i][j] *= sf;
        }
        __syncthreads();   // all KT reads done before P overwrites UN

        // Store P [q][k] into UN (exactly overwrites the 64x128 KT region).
#pragma unroll
        for (int i = 0; i < 8; i++) {
            *(float4*)&UN[(r0 + i) * 128 + cA] =
                make_float4(s[i][0], s[i][1], s[i][2], s[i][3]);
            *(float4*)&UN[(r0 + i) * 128 + cB] =
                make_float4(s[i][4], s[i][5], s[i][6], s[i][7]);
        }
        __syncthreads();

        // O += P V : 8q x 4d per thread, inner over 128 keys.
#pragma unroll 2
        for (int k4 = 0; k4 < 32; k4++) {
            float4 v0 = *(const float4*)&Vs[(k4 * 4 + 0) * 64 + tx * 4];
            float4 v1 = *(const float4*)&Vs[(k4 * 4 + 1) * 64 + tx * 4];
            float4 v2 = *(const float4*)&Vs[(k4 * 4 + 2) * 64 + tx * 4];
            float4 v3 = *(const float4*)&Vs[(k4 * 4 + 3) * 64 + tx * 4];
            float bv[4][4] = {{v0.x, v0.y, v0.z, v0.w},
                              {v1.x, v1.y, v1.z, v1.w},
                              {v2.x, v2.y, v2.z, v2.w},
                              {v3.x, v3.y, v3.z, v3.w}};
#pragma unroll
            for (int i = 0; i < 8; i++) {
                float4 a4 = *(const float4*)&UN[(r0 + i) * 128 + k4 * 4];
                float aa[4] = {a4.x, a4.y, a4.z, a4.w};
#pragma unroll
                for (int c = 0; c < 4; c++)
#pragma unroll
                    for (int jj = 0; jj < 4; jj++)
                        acc[i][c] = fmaf(aa[jj], bv[jj][c], acc[i][c]);
            }
        }
    }

    // Epilogue: out[b][s][h*64 + tx*4 ..]
#pragma unroll
    for (int i = 0; i < 8; i++) {
        float inv = 1.0f / lsum[i];
        float4 o = make_float4(acc[i][0] * inv, acc[i][1] * inv,
                               acc[i][2] * inv, acc[i][3] * inv);
        int srow = q0 + r0 + i;
        *(float4*)(out + ((size_t)(b * SEQ + srow)) * HID + h * HDIM + tx * 4) = o;
    }
}

extern "C" void kernel_launch(void* const* d_in, const int* in_sizes, int n_in,
                              void* d_out, int out_size) {
    const float* X    = (const float*)d_in[0];
    const int*   mask = (const int*)d_in[1];
    const float* Wq   = (const float*)d_in[2];
    const float* Bq   = (const float*)d_in[3];
    const float* Wk   = (const float*)d_in[4];
    const float* Bk   = (const float*)d_in[5];
    const float* Wv   = (const float*)d_in[6];
    const float* Bv   = (const float*)d_in[7];
    float* out = (float*)d_out;

    dim3 g1(HID / 128, (BATCH * SEQ) / 128, 3);
    qkv_kernel<<<g1, 256>>>(X, Wq, Bq, Wk, Bk, Wv, Bv);

    static const int smem_bytes = 80 * 1024;   // 2 CTAs/SM
    cudaFuncSetAttribute(attn_kernel,
                         cudaFuncAttributeMaxDynamicSharedMemorySize, smem_bytes);
    dim3 g2(SEQ / 64, BATCH * NHEAD);
    attn_kernel<<<g2, 128, smem_bytes>>>(mask, out);
}

// round 9
// speedup vs baseline: 1.3175x; 1.2049x over previous
#include <cuda_runtime.h>
#include <cuda_bf16.h>
#include <cstdint>

#define BATCH 4
#define SEQ   2048
#define NHEAD 16
#define HDIM  64
#define HID   1024
#define NEG_F (-3.4028234663852886e38f)

#define NELT (BATCH * NHEAD * SEQ * HDIM)

// Scratch: Q/K as bf16 hi/lo split pairs, V fp32. [b*NH + h][s][d] layout.
__device__ __nv_bfloat16 g_qh[NELT];
__device__ __nv_bfloat16 g_ql[NELT];
__device__ __nv_bfloat16 g_kh[NELT];
__device__ __nv_bfloat16 g_kl[NELT];
__device__ float         g_v [NELT];

__device__ __forceinline__ float neg_inf_f() { return __int_as_float(0xff800000); }

__device__ __forceinline__ void mma16816(float* d, const uint32_t* a, const uint32_t* b) {
    asm volatile(
        "mma.sync.aligned.m16n8k16.row.col.f32.bf16.bf16.f32 "
        "{%0,%1,%2,%3}, {%4,%5,%6,%7}, {%8,%9}, {%0,%1,%2,%3};"
        : "+f"(d[0]), "+f"(d[1]), "+f"(d[2]), "+f"(d[3])
        : "r"(a[0]), "r"(a[1]), "r"(a[2]), "r"(a[3]), "r"(b[0]), "r"(b[1]));
}

__device__ __forceinline__ uint32_t pack_bf16(__nv_bfloat16 lo, __nv_bfloat16 hi) {
    return ((uint32_t)__bfloat16_as_ushort(hi) << 16) | __bfloat16_as_ushort(lo);
}

// ---------------------------------------------------------------------------
// Kernel 1: Y = X @ W + b (z selects q/k/v). SIMT fp32 (measured ~fp32 peak).
// Epilogue: z<2 -> split each value into bf16 hi/lo (g_qh/g_ql or g_kh/g_kl);
// z==2 -> fp32 g_v. All in [bh][s][d] layout.
// ---------------------------------------------------------------------------
__global__ __launch_bounds__(256) void qkv_kernel(
    const float* __restrict__ X,
    const float* __restrict__ Wq, const float* __restrict__ Bq,
    const float* __restrict__ Wk, const float* __restrict__ Bk,
    const float* __restrict__ Wv, const float* __restrict__ Bv)
{
    const int z = blockIdx.z;
    const float* __restrict__ W  = (z == 0) ? Wq : (z == 1) ? Wk : Wv;
    const float* __restrict__ Bi = (z == 0) ? Bq : (z == 1) ? Bk : Bv;

    __shared__ float XsT[16][132];
    __shared__ float Ws[16][128];

    const int tid = threadIdx.x;
    const int tx  = tid & 15;
    const int ty  = tid >> 4;
    const int m0  = blockIdx.y * 128;
    const int n0  = blockIdx.x * 128;

    float acc[8][8];
#pragma unroll
    for (int i = 0; i < 8; i++)
#pragma unroll
        for (int j = 0; j < 8; j++) acc[i][j] = 0.f;

    for (int k0 = 0; k0 < HID; k0 += 16) {
#pragma unroll
        for (int p = 0; p < 2; p++) {
            int i  = tid + p * 256;
            int ml = i >> 2;
            int kq = i & 3;
            float4 v = *(const float4*)(X + (size_t)(m0 + ml) * HID + k0 + kq * 4);
            XsT[kq * 4 + 0][ml] = v.x;
            XsT[kq * 4 + 1][ml] = v.y;
            XsT[kq * 4 + 2][ml] = v.z;
            XsT[kq * 4 + 3][ml] = v.w;
        }
#pragma unroll
        for (int p = 0; p < 2; p++) {
            int i  = tid + p * 256;
            int kr = i >> 5;
            int nq = i & 31;
            float4 v = *(const float4*)(W + (size_t)(k0 + kr) * HID + n0 + nq * 4);
            *(float4*)&Ws[kr][nq * 4] = v;
        }
        __syncthreads();
#pragma unroll
        for (int kk = 0; kk < 16; kk++) {
            float4 a0 = *(const float4*)&XsT[kk][ty * 8];
            float4 a1 = *(const float4*)&XsT[kk][ty * 8 + 4];
            float4 b0 = *(const float4*)&Ws[kk][tx * 8];
            float4 b1 = *(const float4*)&Ws[kk][tx * 8 + 4];
            float a[8] = {a0.x, a0.y, a0.z, a0.w, a1.x, a1.y, a1.z, a1.w};
            float bb[8] = {b0.x, b0.y, b0.z, b0.w, b1.x, b1.y, b1.z, b1.w};
#pragma unroll
            for (int i = 0; i < 8; i++)
#pragma unroll
                for (int j = 0; j < 8; j++)
                    acc[i][j] = fmaf(a[i], bb[j], acc[i][j]);
        }
        __syncthreads();
    }

    const int ncol = n0 + tx * 8;
    const int h    = ncol >> 6;
    const int d0   = ncol & 63;
    float4 bA = *(const float4*)(Bi + ncol);
    float4 bB = *(const float4*)(Bi + ncol + 4);
    const float bb[8] = {bA.x, bA.y, bA.z, bA.w, bB.x, bB.y, bB.z, bB.w};

    if (z == 2) {
#pragma unroll
        for (int i = 0; i < 8; i++) {
            int m = m0 + ty * 8 + i;
            int bi = m >> 11;
            int s  = m & (SEQ - 1);
            float* p = g_v + ((size_t)(bi * NHEAD + h) * SEQ + s) * HDIM + d0;
            float4 o0, o1;
            o0.x = acc[i][0] + bb[0]; o0.y = acc[i][1] + bb[1];
            o0.z = acc[i][2] + bb[2]; o0.w = acc[i][3] + bb[3];
            o1.x = acc[i][4] + bb[4]; o1.y = acc[i][5] + bb[5];
            o1.z = acc[i][6] + bb[6]; o1.w = acc[i][7] + bb[7];
            *(float4*)(p)     = o0;
            *(float4*)(p + 4) = o1;
        }
    } else {
        __nv_bfloat16* dh = (z == 0) ? g_qh : g_kh;
        __nv_bfloat16* dl = (z == 0) ? g_ql : g_kl;
#pragma unroll
        for (int i = 0; i < 8; i++) {
            int m = m0 + ty * 8 + i;
            int bi = m >> 11;
            int s  = m & (SEQ - 1);
            size_t off = ((size_t)(bi * NHEAD + h) * SEQ + s) * HDIM + d0;
            uint4 uh, ul;
            uint32_t* ph = (uint32_t*)&uh;
            uint32_t* pl = (uint32_t*)&ul;
#pragma unroll
            for (int j = 0; j < 4; j++) {
                float f0 = acc[i][2 * j]     + bb[2 * j];
                float f1 = acc[i][2 * j + 1] + bb[2 * j + 1];
                __nv_bfloat16 h0 = __float2bfloat16(f0);
                __nv_bfloat16 h1 = __float2bfloat16(f1);
                __nv_bfloat16 l0 = __float2bfloat16(f0 - __bfloat162float(h0));
                __nv_bfloat16 l1 = __float2bfloat16(f1 - __bfloat162float(h1));
                ph[j] = pack_bf16(h0, h1);
                pl[j] = pack_bf16(l0, l1);
            }
            *(uint4*)(dh + off) = uh;
            *(uint4*)(dl + off) = ul;
        }
    }
}

// ---------------------------------------------------------------------------
// Kernel 2: flash attention, BQ=128 x BK=128, 256 threads (8 warps).
// S = Q K^T via bf16x3-split mma.sync (warp w owns q-rows 16w..16w+15, all
// 128 k-cols). Softmax on C-fragments (row spread over 4 t-lanes -> 2 shfls).
// PV stays SIMT fp32. Per-row sf/l bridged through smem.
// Smem (dynamic):
//   Qh,Ql bf16[128][72]   bytes 0 / 18432        (pad 72: frag banks 4g+t)
//   UN: Kh,Kl bf16[128][72] at 36864 / 55296, aliased by P fp32[128][132]
//   Vs fp32[128][64]      at 104448
//   sfs[128], ls[128]     at 137216 / 137728     (total 138240 B)
// ---------------------------------------------------------------------------
__global__ __launch_bounds__(256) void attn_kernel(
    const int* __restrict__ mask,
    float* __restrict__ out)
{
    extern __shared__ char smraw[];
    __nv_bfloat16* Qh = (__nv_bfloat16*)smraw;            // 128*72
    __nv_bfloat16* Ql = Qh + 128 * 72;
    __nv_bfloat16* Kh = (__nv_bfloat16*)(smraw + 36864);  // 128*72
    __nv_bfloat16* Kl = Kh + 128 * 72;
    float* P   = (float*)(smraw + 36864);                 // [128][132] alias over Kh/Kl
    float* Vs  = (float*)(smraw + 104448);                // [128][64]
    float* sfs = (float*)(smraw + 137216);                // [128]
    float* ls  = (float*)(smraw + 137728);                // [128]

    const int tid  = threadIdx.x;
    const int warp = tid >> 5;
    const int lane = tid & 31;
    const int g    = lane >> 2;
    const int t    = lane & 3;
    const int rlo  = warp * 16 + g;      // S-phase rows
    const int rhi  = rlo + 8;
    const int tx   = tid & 15;           // PV mapping (round-6 proven)
    const int ty   = tid >> 4;
    const int r0   = ty * 8;

    const int q0 = blockIdx.x * 128;
    const int bh = blockIdx.y;
    const int b  = bh >> 4;
    const int h  = bh & 15;

    const __nv_bfloat16* Qgh = g_qh + (size_t)bh * SEQ * HDIM;
    const __nv_bfloat16* Qgl = g_ql + (size_t)bh * SEQ * HDIM;
    const __nv_bfloat16* Kgh = g_kh + (size_t)bh * SEQ * HDIM;
    const __nv_bfloat16* Kgl = g_kl + (size_t)bh * SEQ * HDIM;
    const float*         Vg  = g_v  + (size_t)bh * SEQ * HDIM;
    const int* __restrict__ mrow = mask + (size_t)b * SEQ;

    // Load Q hi/lo (128 rows x 64 bf16 = 8 x 16B per row). 1024 uint4 each.
#pragma unroll
    for (int p = 0; p < 4; p++) {
        int idx = tid + p * 256;
        int row = idx >> 3;
        int seg = idx & 7;
        uint4 vh = *(const uint4*)(Qgh + (size_t)(q0 + row) * HDIM + seg * 8);
        uint4 vl = *(const uint4*)(Qgl + (size_t)(q0 + row) * HDIM + seg * 8);
        *(uint4*)&Qh[row * 72 + seg * 8] = vh;
        *(uint4*)&Ql[row * 72 + seg * 8] = vl;
    }

    float acc[8][4];
#pragma unroll
    for (int i = 0; i < 8; i++)
#pragma unroll
        for (int j = 0; j < 4; j++) acc[i][j] = 0.f;
    float mpl = neg_inf_f(), mph = neg_inf_f();
    float lsl = 0.f, lsh = 0.f;

    for (int kt = 0; kt < SEQ / 128; kt++) {
        const int k0 = kt * 128;
        __syncthreads();   // prev PV done; (iter 0) Q visible

        // Load K hi/lo into UN, V into Vs.
#pragma unroll
        for (int p = 0; p < 4; p++) {
            int idx = tid + p * 256;
            int row = idx >> 3;
            int seg = idx & 7;
            uint4 vh = *(const uint4*)(Kgh + (size_t)(k0 + row) * HDIM + seg * 8);
            uint4 vl = *(const uint4*)(Kgl + (size_t)(k0 + row) * HDIM + seg * 8);
            *(uint4*)&Kh[row * 72 + seg * 8] = vh;
            *(uint4*)&Kl[row * 72 + seg * 8] = vl;
        }
#pragma unroll
        for (int p = 0; p < 8; p++) {
            int idx = tid + p * 256;
            int vl2 = idx >> 4, dv = idx & 15;
            float4 w = *(const float4*)(Vg + (size_t)(k0 + vl2) * HDIM + dv * 4);
            *(float4*)&Vs[vl2 * 64 + dv * 4] = w;
        }
        __syncthreads();

        // S = Q K^T via 3-term split mma. s[j][*]: cols {8j+2t, 8j+2t+1},
        // rows rlo (e0,e1) / rhi (e2,e3).
        float s[16][4];
#pragma unroll
        for (int j = 0; j < 16; j++)
#pragma unroll
            for (int e = 0; e < 4; e++) s[j][e] = 0.f;

#pragma unroll
        for (int ks = 0; ks < 4; ks++) {
            const int kb = ks * 16 + 2 * t;
            uint32_t Ah[4], Al[4];
            Ah[0] = *(const uint32_t*)&Qh[rlo * 72 + kb];
            Ah[1] = *(const uint32_t*)&Qh[rhi * 72 + kb];
            Ah[2] = *(const uint32_t*)&Qh[rlo * 72 + kb + 8];
            Ah[3] = *(const uint32_t*)&Qh[rhi * 72 + kb + 8];
            Al[0] = *(const uint32_t*)&Ql[rlo * 72 + kb];
            Al[1] = *(const uint32_t*)&Ql[rhi * 72 + kb];
            Al[2] = *(const uint32_t*)&Ql[rlo * 72 + kb + 8];
            Al[3] = *(const uint32_t*)&Ql[rhi * 72 + kb + 8];
#pragma unroll
            for (int j = 0; j < 16; j++) {
                const int crow = 8 * j + g;
                uint32_t Bh[2], Bl[2];
                Bh[0] = *(const uint32_t*)&Kh[crow * 72 + kb];
                Bh[1] = *(const uint32_t*)&Kh[crow * 72 + kb + 8];
                Bl[0] = *(const uint32_t*)&Kl[crow * 72 + kb];
                Bl[1] = *(const uint32_t*)&Kl[crow * 72 + kb + 8];
                mma16816(s[j], Ah, Bh);
                mma16816(s[j], Ah, Bl);
                mma16816(s[j], Al, Bh);
            }
        }

        // Softmax on fragments. Scale 1/8, bias, row-max/-sum over 32 local
        // cols + xor{1,2} across the 4 t-lanes sharing each row.
        float mxl = neg_inf_f(), mxh = neg_inf_f();
#pragma unroll
        for (int j = 0; j < 16; j++) {
            float b0 = (mrow[k0 + 8 * j + 2 * t]     != 0) ? 0.f : NEG_F;
            float b1 = (mrow[k0 + 8 * j + 2 * t + 1] != 0) ? 0.f : NEG_F;
            s[j][0] = fmaf(s[j][0], 0.125f, b0);
            s[j][1] = fmaf(s[j][1], 0.125f, b1);
            s[j][2] = fmaf(s[j][2], 0.125f, b0);
            s[j][3] = fmaf(s[j][3], 0.125f, b1);
            mxl = fmaxf(mxl, fmaxf(s[j][0], s[j][1]));
            mxh = fmaxf(mxh, fmaxf(s[j][2], s[j][3]));
        }
        mxl = fmaxf(mxl, __shfl_xor_sync(0xffffffffu, mxl, 1));
        mxl = fmaxf(mxl, __shfl_xor_sync(0xffffffffu, mxl, 2));
        mxh = fmaxf(mxh, __shfl_xor_sync(0xffffffffu, mxh, 1));
        mxh = fmaxf(mxh, __shfl_xor_sync(0xffffffffu, mxh, 2));
        float mnl = fmaxf(mpl, mxl);
        float mnh = fmaxf(mph, mxh);
        float sfl = __expf(mpl - mnl);
        float sfh = __expf(mph - mnh);
        float rsl = 0.f, rsh = 0.f;
#pragma unroll
        for (int j = 0; j < 16; j++) {
            s[j][0] = __expf(s[j][0] - mnl); rsl += s[j][0];
            s[j][1] = __expf(s[j][1] - mnl); rsl += s[j][1];
            s[j][2] = __expf(s[j][2] - mnh); rsh += s[j][2];
            s[j][3] = __expf(s[j][3] - mnh); rsh += s[j][3];
        }
        rsl += __shfl_xor_sync(0xffffffffu, rsl, 1);
        rsl += __shfl_xor_sync(0xffffffffu, rsl, 2);
        rsh += __shfl_xor_sync(0xffffffffu, rsh, 1);
        rsh += __shfl_xor_sync(0xffffffffu, rsh, 2);
        lsl = lsl * sfl + rsl;
        lsh = lsh * sfh + rsh;
        mpl = mnl;
        mph = mnh;
        if (t == 0) {
            sfs[rlo] = sfl; sfs[rhi] = sfh;
            ls[rlo]  = lsl; ls[rhi]  = lsh;
        }
        __syncthreads();   // all K-frag reads done before P overwrites UN

        // Store P (fp32, stride 132) into UN.
#pragma unroll
        for (int j = 0; j < 16; j++) {
            *(float2*)&P[rlo * 132 + 8 * j + 2 * t] = make_float2(s[j][0], s[j][1]);
            *(float2*)&P[rhi * 132 + 8 * j + 2 * t] = make_float2(s[j][2], s[j][3]);
        }
        __syncthreads();

        // Rescale O by this tile's row factors, then O += P V (SIMT fp32).
#pragma unroll
        for (int i = 0; i < 8; i++) {
            float sf = sfs[r0 + i];
#pragma unroll
            for (int c = 0; c < 4; c++) acc[i][c] *= sf;
        }
#pragma unroll 2
        for (int k4 = 0; k4 < 32; k4++) {
            float4 v0 = *(const float4*)&Vs[(k4 * 4 + 0) * 64 + tx * 4];
            float4 v1 = *(const float4*)&Vs[(k4 * 4 + 1) * 64 + tx * 4];
            float4 v2 = *(const float4*)&Vs[(k4 * 4 + 2) * 64 + tx * 4];
            float4 v3 = *(const float4*)&Vs[(k4 * 4 + 3) * 64 + tx * 4];
            float bv[4][4] = {{v0.x, v0.y, v0.z, v0.w},
                              {v1.x, v1.y, v1.z, v1.w},
                              {v2.x, v2.y, v2.z, v2.w},
                              {v3.x, v3.y, v3.z, v3.w}};
#pragma unroll
            for (int i = 0; i < 8; i++) {
                float4 a4 = *(const float4*)&P[(r0 + i) * 132 + k4 * 4];
                float aa[4] = {a4.x, a4.y, a4.z, a4.w};
#pragma unroll
                for (int c = 0; c < 4; c++)
#pragma unroll
                    for (int jj = 0; jj < 4; jj++)
                        acc[i][c] = fmaf(aa[jj], bv[jj][c], acc[i][c]);
            }
        }
    }

    // Epilogue: out[b][s][h*64 + tx*4..] = acc / l  (ls stable since last tile)
#pragma unroll
    for (int i = 0; i < 8; i++) {
        float inv = 1.0f / ls[r0 + i];
        float4 o = make_float4(acc[i][0] * inv, acc[i][1] * inv,
                               acc[i][2] * inv, acc[i][3] * inv);
        int srow = q0 + r0 + i;
        *(float4*)(out + ((size_t)(b * SEQ + srow)) * HID + h * HDIM + tx * 4) = o;
    }
}

extern "C" void kernel_launch(void* const* d_in, const int* in_sizes, int n_in,
                              void* d_out, int out_size) {
    const float* X    = (const float*)d_in[0];
    const int*   mask = (const int*)d_in[1];
    const float* Wq   = (const float*)d_in[2];
    const float* Bq   = (const float*)d_in[3];
    const float* Wk   = (const float*)d_in[4];
    const float* Bk   = (const float*)d_in[5];
    const float* Wv   = (const float*)d_in[6];
    const float* Bv   = (const float*)d_in[7];
    float* out = (float*)d_out;

    dim3 g1(HID / 128, (BATCH * SEQ) / 128, 3);
    qkv_kernel<<<g1, 256>>>(X, Wq, Bq, Wk, Bk, Wv, Bv);

    static const int smem_bytes = 138240;
    cudaFuncSetAttribute(attn_kernel,
                         cudaFuncAttributeMaxDynamicSharedMemorySize, smem_bytes);
    dim3 g2(SEQ / 128, BATCH * NHEAD);
    attn_kernel<<<g2, 256, smem_bytes>>>(mask, out);
}

// round 10
// speedup vs baseline: 1.4062x; 1.0673x over previous
#include <cuda_runtime.h>
#include <cuda_bf16.h>
#include <cstdint>

#define BATCH 4
#define SEQ   2048
#define NHEAD 16
#define HDIM  64
#define HID   1024
#define NEG_F (-3.4028234663852886e38f)

#define NELT (BATCH * NHEAD * SEQ * HDIM)

// Scratch: Q/K bf16 hi/lo in [bh][s][d]; V bf16 hi/lo TRANSPOSED [bh][d][s].
__device__ __nv_bfloat16 g_qh[NELT];
__device__ __nv_bfloat16 g_ql[NELT];
__device__ __nv_bfloat16 g_kh[NELT];
__device__ __nv_bfloat16 g_kl[NELT];
__device__ __nv_bfloat16 g_vh[NELT];
__device__ __nv_bfloat16 g_vl[NELT];

__device__ __forceinline__ float neg_inf_f() { return __int_as_float(0xff800000); }

__device__ __forceinline__ void mma16816(float* d, const uint32_t* a, const uint32_t* b) {
    asm volatile(
        "mma.sync.aligned.m16n8k16.row.col.f32.bf16.bf16.f32 "
        "{%0,%1,%2,%3}, {%4,%5,%6,%7}, {%8,%9}, {%0,%1,%2,%3};"
        : "+f"(d[0]), "+f"(d[1]), "+f"(d[2]), "+f"(d[3])
        : "r"(a[0]), "r"(a[1]), "r"(a[2]), "r"(a[3]), "r"(b[0]), "r"(b[1]));
}

__device__ __forceinline__ uint32_t pack_bf16(__nv_bfloat16 lo, __nv_bfloat16 hi) {
    return ((uint32_t)__bfloat16_as_ushort(hi) << 16) | __bfloat16_as_ushort(lo);
}

__device__ __forceinline__ void split2(float f, uint16_t& h, uint16_t& l) {
    __nv_bfloat16 hb = __float2bfloat16(f);
    __nv_bfloat16 lb = __float2bfloat16(f - __bfloat162float(hb));
    h = __bfloat16_as_ushort(hb);
    l = __bfloat16_as_ushort(lb);
}

// ---------------------------------------------------------------------------
// Kernel 1: Y = X @ W + b (z selects q/k/v). SIMT fp32 mainloop (~fp32 peak).
// Epilogue: z<2 -> bf16 hi/lo [bh][s][d]; z==2 -> bf16 hi/lo TRANSPOSED
// [bh][d][s] (thread's 8 consecutive s pack into one uint4 per d-col).
// ---------------------------------------------------------------------------
__global__ __launch_bounds__(256) void qkv_kernel(
    const float* __restrict__ X,
    const float* __restrict__ Wq, const float* __restrict__ Bq,
    const float* __restrict__ Wk, const float* __restrict__ Bk,
    const float* __restrict__ Wv, const float* __restrict__ Bv)
{
    const int z = blockIdx.z;
    const float* __restrict__ W  = (z == 0) ? Wq : (z == 1) ? Wk : Wv;
    const float* __restrict__ Bi = (z == 0) ? Bq : (z == 1) ? Bk : Bv;

    __shared__ float XsT[16][132];
    __shared__ float Ws[16][128];

    const int tid = threadIdx.x;
    const int tx  = tid & 15;
    const int ty  = tid >> 4;
    const int m0  = blockIdx.y * 128;
    const int n0  = blockIdx.x * 128;

    float acc[8][8];
#pragma unroll
    for (int i = 0; i < 8; i++)
#pragma unroll
        for (int j = 0; j < 8; j++) acc[i][j] = 0.f;

    for (int k0 = 0; k0 < HID; k0 += 16) {
#pragma unroll
        for (int p = 0; p < 2; p++) {
            int i  = tid + p * 256;
            int ml = i >> 2;
            int kq = i & 3;
            float4 v = *(const float4*)(X + (size_t)(m0 + ml) * HID + k0 + kq * 4);
            XsT[kq * 4 + 0][ml] = v.x;
            XsT[kq * 4 + 1][ml] = v.y;
            XsT[kq * 4 + 2][ml] = v.z;
            XsT[kq * 4 + 3][ml] = v.w;
        }
#pragma unroll
        for (int p = 0; p < 2; p++) {
            int i  = tid + p * 256;
            int kr = i >> 5;
            int nq = i & 31;
            float4 v = *(const float4*)(W + (size_t)(k0 + kr) * HID + n0 + nq * 4);
            *(float4*)&Ws[kr][nq * 4] = v;
        }
        __syncthreads();
#pragma unroll
        for (int kk = 0; kk < 16; kk++) {
            float4 a0 = *(const float4*)&XsT[kk][ty * 8];
            float4 a1 = *(const float4*)&XsT[kk][ty * 8 + 4];
            float4 b0 = *(const float4*)&Ws[kk][tx * 8];
            float4 b1 = *(const float4*)&Ws[kk][tx * 8 + 4];
            float a[8] = {a0.x, a0.y, a0.z, a0.w, a1.x, a1.y, a1.z, a1.w};
            float bb[8] = {b0.x, b0.y, b0.z, b0.w, b1.x, b1.y, b1.z, b1.w};
#pragma unroll
            for (int i = 0; i < 8; i++)
#pragma unroll
                for (int j = 0; j < 8; j++)
                    acc[i][j] = fmaf(a[i], bb[j], acc[i][j]);
        }
        __syncthreads();
    }

    const int ncol = n0 + tx * 8;
    const int h    = ncol >> 6;
    const int d0   = ncol & 63;
    float4 bA = *(const float4*)(Bi + ncol);
    float4 bB = *(const float4*)(Bi + ncol + 4);
    const float bb[8] = {bA.x, bA.y, bA.z, bA.w, bB.x, bB.y, bB.z, bB.w};

    if (z == 2) {
        // V: split + transpose. All 8 rows share one (bi, s0) block.
        const int mbase = m0 + ty * 8;
        const int bi = mbase >> 11;
        const int s0 = mbase & (SEQ - 1);
#pragma unroll
        for (int j = 0; j < 8; j++) {
            uint16_t hs[8], ls_[8];
#pragma unroll
            for (int i = 0; i < 8; i++)
                split2(acc[i][j] + bb[j], hs[i], ls_[i]);
            uint4 uh, ul;
            uint32_t* ph = (uint32_t*)&uh;
            uint32_t* pl = (uint32_t*)&ul;
#pragma unroll
            for (int w2 = 0; w2 < 4; w2++) {
                ph[w2] = ((uint32_t)hs[2 * w2 + 1] << 16) | hs[2 * w2];
                pl[w2] = ((uint32_t)ls_[2 * w2 + 1] << 16) | ls_[2 * w2];
            }
            size_t off = ((size_t)(bi * NHEAD + h) * HDIM + d0 + j) * SEQ + s0;
            *(uint4*)(g_vh + off) = uh;
            *(uint4*)(g_vl + off) = ul;
        }
    } else {
        __nv_bfloat16* dh = (z == 0) ? g_qh : g_kh;
        __nv_bfloat16* dl = (z == 0) ? g_ql : g_kl;
#pragma unroll
        for (int i = 0; i < 8; i++) {
            int m = m0 + ty * 8 + i;
            int bi = m >> 11;
            int s  = m & (SEQ - 1);
            size_t off = ((size_t)(bi * NHEAD + h) * SEQ + s) * HDIM + d0;
            uint4 uh, ul;
            uint32_t* ph = (uint32_t*)&uh;
            uint32_t* pl = (uint32_t*)&ul;
#pragma unroll
            for (int j = 0; j < 4; j++) {
                uint16_t h0, l0, h1, l1;
                split2(acc[i][2 * j]     + bb[2 * j],     h0, l0);
                split2(acc[i][2 * j + 1] + bb[2 * j + 1], h1, l1);
                ph[j] = ((uint32_t)h1 << 16) | h0;
                pl[j] = ((uint32_t)l1 << 16) | l0;
            }
            *(uint4*)(dh + off) = uh;
            *(uint4*)(dl + off) = ul;
        }
    }
}

// ---------------------------------------------------------------------------
// Kernel 2: flash attention, BQ=128 x BK=128, 256 threads (8 warps).
// Both S = QK^T and O += PV via bf16x3-split mma.sync. Warp w owns q-rows
// 16w..16w+15 in BOTH phases -> softmax state (m, l, sf) stays in registers.
// Smem (dynamic, 141312 B):
//   Qh,Ql  bf16[128][72]   @ 0      / 18432
//   UN     @ 36864: Kh,Kl bf16[128][72] (@36864/55296), aliased after the S
//          phase by Ph,Pl bf16[128][136] (@36864/71680)
//   VhT,VlT bf16[64][136]  @ 106496 / 123904   (V^T: [d][k], k contiguous)
// ---------------------------------------------------------------------------
__global__ __launch_bounds__(256) void attn_kernel(
    const int* __restrict__ mask,
    float* __restrict__ out)
{
    extern __shared__ char smraw[];
    __nv_bfloat16* Qh  = (__nv_bfloat16*)smraw;
    __nv_bfloat16* Ql  = (__nv_bfloat16*)(smraw + 18432);
    __nv_bfloat16* Kh  = (__nv_bfloat16*)(smraw + 36864);
    __nv_bfloat16* Kl  = (__nv_bfloat16*)(smraw + 55296);
    __nv_bfloat16* Ph  = (__nv_bfloat16*)(smraw + 36864);   // alias over Kh/Kl
    __nv_bfloat16* Pl  = (__nv_bfloat16*)(smraw + 71680);
    __nv_bfloat16* VhT = (__nv_bfloat16*)(smraw + 106496);
    __nv_bfloat16* VlT = (__nv_bfloat16*)(smraw + 123904);

    const int tid  = threadIdx.x;
    const int warp = tid >> 5;
    const int lane = tid & 31;
    const int g    = lane >> 2;
    const int t    = lane & 3;
    const int rlo  = warp * 16 + g;
    const int rhi  = rlo + 8;

    const int q0 = blockIdx.x * 128;
    const int bh = blockIdx.y;
    const int b  = bh >> 4;
    const int h  = bh & 15;

    const __nv_bfloat16* Qgh = g_qh + (size_t)bh * SEQ * HDIM;
    const __nv_bfloat16* Qgl = g_ql + (size_t)bh * SEQ * HDIM;
    const __nv_bfloat16* Kgh = g_kh + (size_t)bh * SEQ * HDIM;
    const __nv_bfloat16* Kgl = g_kl + (size_t)bh * SEQ * HDIM;
    const __nv_bfloat16* Vgh = g_vh + (size_t)bh * SEQ * HDIM;   // [d][s]
    const __nv_bfloat16* Vgl = g_vl + (size_t)bh * SEQ * HDIM;
    const int* __restrict__ mrow = mask + (size_t)b * SEQ;

    // Load Q hi/lo (128 x 64 bf16).
#pragma unroll
    for (int p = 0; p < 4; p++) {
        int idx = tid + p * 256;
        int row = idx >> 3;
        int seg = idx & 7;
        uint4 vh = *(const uint4*)(Qgh + (size_t)(q0 + row) * HDIM + seg * 8);
        uint4 vl = *(const uint4*)(Qgl + (size_t)(q0 + row) * HDIM + seg * 8);
        *(uint4*)&Qh[row * 72 + seg * 8] = vh;
        *(uint4*)&Ql[row * 72 + seg * 8] = vl;
    }

    float acc[8][4];   // O fragments: cols 8f+2t(+1), rows rlo(e0,e1)/rhi(e2,e3)
#pragma unroll
    for (int f = 0; f < 8; f++)
#pragma unroll
        for (int e = 0; e < 4; e++) acc[f][e] = 0.f;
    float mpl = neg_inf_f(), mph = neg_inf_f();
    float lsl = 0.f, lsh = 0.f;

    for (int kt = 0; kt < SEQ / 128; kt++) {
        const int k0 = kt * 128;
        __syncthreads();   // prev PV reads done; (iter 0) Q visible

        // Stage K hi/lo [s][d] and V^T hi/lo [d][s-slice].
#pragma unroll
        for (int p = 0; p < 4; p++) {
            int idx = tid + p * 256;
            int row = idx >> 3;
            int seg = idx & 7;
            uint4 vh = *(const uint4*)(Kgh + (size_t)(k0 + row) * HDIM + seg * 8);
            uint4 vl = *(const uint4*)(Kgl + (size_t)(k0 + row) * HDIM + seg * 8);
            *(uint4*)&Kh[row * 72 + seg * 8] = vh;
            *(uint4*)&Kl[row * 72 + seg * 8] = vl;
        }
#pragma unroll
        for (int p = 0; p < 4; p++) {
            int idx = tid + p * 256;       // 0..1023
            int row = idx >> 4;            // d 0..63
            int seg = idx & 15;            // 16 x 8 bf16 = 128 keys
            uint4 vh = *(const uint4*)(Vgh + (size_t)row * SEQ + k0 + seg * 8);
            uint4 vl = *(const uint4*)(Vgl + (size_t)row * SEQ + k0 + seg * 8);
            *(uint4*)&VhT[row * 136 + seg * 8] = vh;
            *(uint4*)&VlT[row * 136 + seg * 8] = vl;
        }
        __syncthreads();

        // ---- S = Q K^T (3-term split mma) ----
        float s[16][4];
#pragma unroll
        for (int j = 0; j < 16; j++)
#pragma unroll
            for (int e = 0; e < 4; e++) s[j][e] = 0.f;

#pragma unroll
        for (int ks = 0; ks < 4; ks++) {
            const int kb = ks * 16 + 2 * t;
            uint32_t Ah[4], Al[4];
            Ah[0] = *(const uint32_t*)&Qh[rlo * 72 + kb];
            Ah[1] = *(const uint32_t*)&Qh[rhi * 72 + kb];
            Ah[2] = *(const uint32_t*)&Qh[rlo * 72 + kb + 8];
            Ah[3] = *(const uint32_t*)&Qh[rhi * 72 + kb + 8];
            Al[0] = *(const uint32_t*)&Ql[rlo * 72 + kb];
            Al[1] = *(const uint32_t*)&Ql[rhi * 72 + kb];
            Al[2] = *(const uint32_t*)&Ql[rlo * 72 + kb + 8];
            Al[3] = *(const uint32_t*)&Ql[rhi * 72 + kb + 8];
#pragma unroll
            for (int j = 0; j < 16; j++) {
                const int crow = 8 * j + g;
                uint32_t Bh[2], Bl[2];
                Bh[0] = *(const uint32_t*)&Kh[crow * 72 + kb];
                Bh[1] = *(const uint32_t*)&Kh[crow * 72 + kb + 8];
                Bl[0] = *(const uint32_t*)&Kl[crow * 72 + kb];
                Bl[1] = *(const uint32_t*)&Kl[crow * 72 + kb + 8];
                mma16816(s[j], Ah, Bh);
                mma16816(s[j], Ah, Bl);
                mma16816(s[j], Al, Bh);
            }
        }

        // ---- softmax on fragments (rows spread over 4 t-lanes) ----
        float mxl = neg_inf_f(), mxh = neg_inf_f();
#pragma unroll
        for (int j = 0; j < 16; j++) {
            float b0 = (mrow[k0 + 8 * j + 2 * t]     != 0) ? 0.f : NEG_F;
            float b1 = (mrow[k0 + 8 * j + 2 * t + 1] != 0) ? 0.f : NEG_F;
            s[j][0] = fmaf(s[j][0], 0.125f, b0);
            s[j][1] = fmaf(s[j][1], 0.125f, b1);
            s[j][2] = fmaf(s[j][2], 0.125f, b0);
            s[j][3] = fmaf(s[j][3], 0.125f, b1);
            mxl = fmaxf(mxl, fmaxf(s[j][0], s[j][1]));
            mxh = fmaxf(mxh, fmaxf(s[j][2], s[j][3]));
        }
        mxl = fmaxf(mxl, __shfl_xor_sync(0xffffffffu, mxl, 1));
        mxl = fmaxf(mxl, __shfl_xor_sync(0xffffffffu, mxl, 2));
        mxh = fmaxf(mxh, __shfl_xor_sync(0xffffffffu, mxh, 1));
        mxh = fmaxf(mxh, __shfl_xor_sync(0xffffffffu, mxh, 2));
        float mnl = fmaxf(mpl, mxl);
        float mnh = fmaxf(mph, mxh);
        float sfl = __expf(mpl - mnl);
        float sfh = __expf(mph - mnh);
        float rsl = 0.f, rsh = 0.f;
#pragma unroll
        for (int j = 0; j < 16; j++) {
            s[j][0] = __expf(s[j][0] - mnl); rsl += s[j][0];
            s[j][1] = __expf(s[j][1] - mnl); rsl += s[j][1];
            s[j][2] = __expf(s[j][2] - mnh); rsh += s[j][2];
            s[j][3] = __expf(s[j][3] - mnh); rsh += s[j][3];
        }
        rsl += __shfl_xor_sync(0xffffffffu, rsl, 1);
        rsl += __shfl_xor_sync(0xffffffffu, rsl, 2);
        rsh += __shfl_xor_sync(0xffffffffu, rsh, 1);
        rsh += __shfl_xor_sync(0xffffffffu, rsh, 2);
        lsl = lsl * sfl + rsl;
        lsh = lsh * sfh + rsh;
        mpl = mnl;
        mph = mnh;
        __syncthreads();   // all K-frag reads done before P overwrites UN

        // ---- split P to bf16 hi/lo, store in A-operand layout ----
#pragma unroll
        for (int j = 0; j < 16; j++) {
            uint16_t h0, l0, h1, l1, h2, l2, h3, l3;
            split2(s[j][0], h0, l0);
            split2(s[j][1], h1, l1);
            split2(s[j][2], h2, l2);
            split2(s[j][3], h3, l3);
            *(uint32_t*)&Ph[rlo * 136 + 8 * j + 2 * t] = ((uint32_t)h1 << 16) | h0;
            *(uint32_t*)&Pl[rlo * 136 + 8 * j + 2 * t] = ((uint32_t)l1 << 16) | l0;
            *(uint32_t*)&Ph[rhi * 136 + 8 * j + 2 * t] = ((uint32_t)h3 << 16) | h2;
            *(uint32_t*)&Pl[rhi * 136 + 8 * j + 2 * t] = ((uint32_t)l3 << 16) | l2;
        }
        __syncthreads();

        // ---- O = O*sf + P V (3-term split mma) ----
#pragma unroll
        for (int f = 0; f < 8; f++) {
            acc[f][0] *= sfl; acc[f][1] *= sfl;
            acc[f][2] *= sfh; acc[f][3] *= sfh;
        }
#pragma unroll
        for (int ks = 0; ks < 8; ks++) {
            const int kb = ks * 16 + 2 * t;
            uint32_t Ah[4], Al[4];
            Ah[0] = *(const uint32_t*)&Ph[rlo * 136 + kb];
            Ah[1] = *(const uint32_t*)&Ph[rhi * 136 + kb];
            Ah[2] = *(const uint32_t*)&Ph[rlo * 136 + kb + 8];
            Ah[3] = *(const uint32_t*)&Ph[rhi * 136 + kb + 8];
            Al[0] = *(const uint32_t*)&Pl[rlo * 136 + kb];
            Al[1] = *(const uint32_t*)&Pl[rhi * 136 + kb];
            Al[2] = *(const uint32_t*)&Pl[rlo * 136 + kb + 8];
            Al[3] = *(const uint32_t*)&Pl[rhi * 136 + kb + 8];
#pragma unroll
            for (int f = 0; f < 8; f++) {
                const int vr = 8 * f + g;
                uint32_t Bh[2], Bl[2];
                Bh[0] = *(const uint32_t*)&VhT[vr * 136 + kb];
                Bh[1] = *(const uint32_t*)&VhT[vr * 136 + kb + 8];
                Bl[0] = *(const uint32_t*)&VlT[vr * 136 + kb];
                Bl[1] = *(const uint32_t*)&VlT[vr * 136 + kb + 8];
                mma16816(acc[f], Ah, Bh);
                mma16816(acc[f], Ah, Bl);
                mma16816(acc[f], Al, Bh);
            }
        }
    }

    // Epilogue: rows rlo/rhi, cols h*64 + 8f + 2t(+1); divide by l.
    const float invl = 1.0f / lsl;
    const float invh = 1.0f / lsh;
    float* orow_lo = out + ((size_t)(b * SEQ + q0 + rlo)) * HID + h * HDIM;
    float* orow_hi = out + ((size_t)(b * SEQ + q0 + rhi)) * HID + h * HDIM;
#pragma unroll
    for (int f = 0; f < 8; f++) {
        int c = 8 * f + 2 * t;
        *(float2*)(orow_lo + c) = make_float2(acc[f][0] * invl, acc[f][1] * invl);
        *(float2*)(orow_hi + c) = make_float2(acc[f][2] * invh, acc[f][3] * invh);
    }
}

extern "C" void kernel_launch(void* const* d_in, const int* in_sizes, int n_in,
                              void* d_out, int out_size) {
    const float* X    = (const float*)d_in[0];
    const int*   mask = (const int*)d_in[1];
    const float* Wq   = (const float*)d_in[2];
    const float* Bq   = (const float*)d_in[3];
    const float* Wk   = (const float*)d_in[4];
    const float* Bk   = (const float*)d_in[5];
    const float* Wv   = (const float*)d_in[6];
    const float* Bv   = (const float*)d_in[7];
    float* out = (float*)d_out;

    dim3 g1(HID / 128, (BATCH * SEQ) / 128, 3);
    qkv_kernel<<<g1, 256>>>(X, Wq, Bq, Wk, Bk, Wv, Bv);

    static const int smem_bytes = 141312;
    cudaFuncSetAttribute(attn_kernel,
                         cudaFuncAttributeMaxDynamicSharedMemorySize, smem_bytes);
    dim3 g2(SEQ / 128, BATCH * NHEAD);
    attn_kernel<<<g2, 256, smem_bytes>>>(mask, out);
}

// round 11
// speedup vs baseline: 1.8318x; 1.3027x over previous
#include <cuda_runtime.h>
#include <cuda_bf16.h>
#include <cstdint>

#define BATCH 4
#define SEQ   2048
#define NHEAD 16
#define HDIM  64
#define HID   1024
#define NEG_F (-3.4028234663852886e38f)

#define NELT (BATCH * NHEAD * SEQ * HDIM)
#define MTOT (BATCH * SEQ)              // 8192 rows

// Scratch: Q/K bf16 hi/lo in [bh][s][d]; V bf16 hi/lo TRANSPOSED [bh][d][s].
__device__ __nv_bfloat16 g_qh[NELT];
__device__ __nv_bfloat16 g_ql[NELT];
__device__ __nv_bfloat16 g_kh[NELT];
__device__ __nv_bfloat16 g_kl[NELT];
__device__ __nv_bfloat16 g_vh[NELT];
__device__ __nv_bfloat16 g_vl[NELT];
// Pre-split X (hi/lo) and pre-split+transposed Wq/Wk ([n][k], z-major).
__device__ __nv_bfloat16 g_xh[MTOT * HID];
__device__ __nv_bfloat16 g_xl[MTOT * HID];
__device__ __nv_bfloat16 g_wth[2 * HID * HID];
__device__ __nv_bfloat16 g_wtl[2 * HID * HID];

__device__ __forceinline__ float neg_inf_f() { return __int_as_float(0xff800000); }

__device__ __forceinline__ void mma16816(float* d, const uint32_t* a, const uint32_t* b) {
    asm volatile(
        "mma.sync.aligned.m16n8k16.row.col.f32.bf16.bf16.f32 "
        "{%0,%1,%2,%3}, {%4,%5,%6,%7}, {%8,%9}, {%0,%1,%2,%3};"
        : "+f"(d[0]), "+f"(d[1]), "+f"(d[2]), "+f"(d[3])
        : "r"(a[0]), "r"(a[1]), "r"(a[2]), "r"(a[3]), "r"(b[0]), "r"(b[1]));
}

__device__ __forceinline__ void split2(float f, uint16_t& h, uint16_t& l) {
    __nv_bfloat16 hb = __float2bfloat16(f);
    __nv_bfloat16 lb = __float2bfloat16(f - __bfloat162float(hb));
    h = __bfloat16_as_ushort(hb);
    l = __bfloat16_as_ushort(lb);
}

// ---------------------------------------------------------------------------
// split_x: X fp32 -> g_xh/g_xl bf16. 1M threads x 8 elements.
// ---------------------------------------------------------------------------
__global__ __launch_bounds__(256) void split_x_kernel(const float* __restrict__ X) {
    int idx = blockIdx.x * 256 + threadIdx.x;     // 0 .. MTOT*HID/8 - 1
    const float4* xp = (const float4*)X;
    float4 a = xp[idx * 2];
    float4 c = xp[idx * 2 + 1];
    const float f[8] = {a.x, a.y, a.z, a.w, c.x, c.y, c.z, c.w};
    uint4 uh, ul;
    uint32_t* ph = (uint32_t*)&uh;
    uint32_t* pl = (uint32_t*)&ul;
#pragma unroll
    for (int j = 0; j < 4; j++) {
        uint16_t h0, l0, h1, l1;
        split2(f[2 * j],     h0, l0);
        split2(f[2 * j + 1], h1, l1);
        ph[j] = ((uint32_t)h1 << 16) | h0;
        pl[j] = ((uint32_t)l1 << 16) | l0;
    }
    *(uint4*)(g_xh + (size_t)idx * 8) = uh;
    *(uint4*)(g_xl + (size_t)idx * 8) = ul;
}

// ---------------------------------------------------------------------------
// split_wt: W[k][n] fp32 -> transposed bf16 hi/lo [n][k]. 32x32 smem tiles.
// z selects Wq (0) / Wk (1).
// ---------------------------------------------------------------------------
__global__ __launch_bounds__(256) void split_wt_kernel(
    const float* __restrict__ Wq, const float* __restrict__ Wk)
{
    __shared__ uint16_t shh[32 * 33];
    __shared__ uint16_t shl[32 * 33];
    const float* W = (blockIdx.z == 0) ? Wq : Wk;
    const size_t zoff = (size_t)blockIdx.z * HID * HID;
    const int k0 = blockIdx.y * 32;
    const int n0 = blockIdx.x * 32;
    const int tid = threadIdx.x;

#pragma unroll
    for (int p = 0; p < 4; p++) {
        int idx = tid + p * 256;        // 0..1023
        int kl = idx >> 5;              // 0..31
        int nl = idx & 31;
        float f = W[(size_t)(k0 + kl) * HID + n0 + nl];
        uint16_t h, l;
        split2(f, h, l);
        shh[nl * 33 + kl] = h;
        shl[nl * 33 + kl] = l;
    }
    __syncthreads();
#pragma unroll
    for (int p = 0; p < 2; p++) {
        int idx = tid + p * 256;        // 0..511
        int nl = idx >> 4;              // 0..31
        int kp = idx & 15;              // uint32 pair along k
        uint32_t vh = ((uint32_t)shh[nl * 33 + kp * 2 + 1] << 16) | shh[nl * 33 + kp * 2];
        uint32_t vl = ((uint32_t)shl[nl * 33 + kp * 2 + 1] << 16) | shl[nl * 33 + kp * 2];
        size_t off = zoff + (size_t)(n0 + nl) * HID + k0 + kp * 2;
        *(uint32_t*)(g_wth + off) = vh;
        *(uint32_t*)(g_wtl + off) = vl;
    }
}

// ---------------------------------------------------------------------------
// qk_kernel: Q/K projections via bf16x3-split mma (hh+hl+lh), pre-split inputs.
// BM=128, BN=128, BK=32. 8 warps (2m x 4n), warp 64x32, 4x4 m16n8k16 frags.
// Smem rows padded to 40 bf16 (R7-verified conflict-free fragment banks).
// Epilogue -> g_qh/g_ql or g_kh/g_kl in [bh][s][d], bf16 hi/lo.
// ---------------------------------------------------------------------------
__global__ __launch_bounds__(256) void qk_kernel(
    const float* __restrict__ Bq, const float* __restrict__ Bk)
{
    __shared__ __nv_bfloat16 Xhs[128 * 40];
    __shared__ __nv_bfloat16 Xls[128 * 40];
    __shared__ __nv_bfloat16 Whs[128 * 40];
    __shared__ __nv_bfloat16 Wls[128 * 40];

    const int z = blockIdx.z;
    const float* __restrict__ Bi = (z == 0) ? Bq : Bk;
    __nv_bfloat16* dh = (z == 0) ? g_qh : g_kh;
    __nv_bfloat16* dl = (z == 0) ? g_ql : g_kl;
    const __nv_bfloat16* Wth = g_wth + (size_t)z * HID * HID;
    const __nv_bfloat16* Wtl = g_wtl + (size_t)z * HID * HID;

    const int tid  = threadIdx.x;
    const int warp = tid >> 5;
    const int lane = tid & 31;
    const int g    = lane >> 2;
    const int t    = lane & 3;
    const int wm   = (warp >> 2) * 64;
    const int wn   = (warp & 3) * 32;
    const int m0   = blockIdx.y * 128;
    const int n0   = blockIdx.x * 128;

    float D[4][4][4];
#pragma unroll
    for (int fi = 0; fi < 4; fi++)
#pragma unroll
        for (int fj = 0; fj < 4; fj++)
#pragma unroll
            for (int e = 0; e < 4; e++) D[fi][fj][e] = 0.f;

    for (int k0 = 0; k0 < HID; k0 += 32) {
        // Stage X and W^T tiles (128 x 32 bf16 each, hi+lo): uint4 copies.
#pragma unroll
        for (int p = 0; p < 2; p++) {
            int idx = tid + p * 256;     // 0..511
            int row = idx >> 2;          // 0..127
            int seg = idx & 3;           // 4 x 8 bf16 = 32 k
            size_t xs = (size_t)(m0 + row) * HID + k0 + seg * 8;
            *(uint4*)&Xhs[row * 40 + seg * 8] = *(const uint4*)(g_xh + xs);
            *(uint4*)&Xls[row * 40 + seg * 8] = *(const uint4*)(g_xl + xs);
            size_t ws = (size_t)(n0 + row) * HID + k0 + seg * 8;
            *(uint4*)&Whs[row * 40 + seg * 8] = *(const uint4*)(Wth + ws);
            *(uint4*)&Wls[row * 40 + seg * 8] = *(const uint4*)(Wtl + ws);
        }
        __syncthreads();

#pragma unroll
        for (int ks = 0; ks < 2; ks++) {
            const int kb = ks * 16 + 2 * t;
            uint32_t Ah[4][4], Al[4][4];
#pragma unroll
            for (int fi = 0; fi < 4; fi++) {
                int r = wm + fi * 16 + g;
                Ah[fi][0] = *(const uint32_t*)&Xhs[r * 40 + kb];
                Ah[fi][1] = *(const uint32_t*)&Xhs[(r + 8) * 40 + kb];
                Ah[fi][2] = *(const uint32_t*)&Xhs[r * 40 + kb + 8];
                Ah[fi][3] = *(const uint32_t*)&Xhs[(r + 8) * 40 + kb + 8];
                Al[fi][0] = *(const uint32_t*)&Xls[r * 40 + kb];
                Al[fi][1] = *(const uint32_t*)&Xls[(r + 8) * 40 + kb];
                Al[fi][2] = *(const uint32_t*)&Xls[r * 40 + kb + 8];
                Al[fi][3] = *(const uint32_t*)&Xls[(r + 8) * 40 + kb + 8];
            }
#pragma unroll
            for (int fj = 0; fj < 4; fj++) {
                int c = wn + fj * 8 + g;
                uint32_t Bh[2], Bl[2];
                Bh[0] = *(const uint32_t*)&Whs[c * 40 + kb];
                Bh[1] = *(const uint32_t*)&Whs[c * 40 + kb + 8];
                Bl[0] = *(const uint32_t*)&Wls[c * 40 + kb];
                Bl[1] = *(const uint32_t*)&Wls[c * 40 + kb + 8];
#pragma unroll
                for (int fi = 0; fi < 4; fi++) {
                    mma16816(D[fi][fj], Ah[fi], Bh);
                    mma16816(D[fi][fj], Ah[fi], Bl);
                    mma16816(D[fi][fj], Al[fi], Bh);
                }
            }
        }
        __syncthreads();
    }

    // Epilogue: split to bf16 hi/lo, write [bh][s][d].
#pragma unroll
    for (int fj = 0; fj < 4; fj++) {
        const int ncol = n0 + wn + fj * 8 + 2 * t;
        const int h    = ncol >> 6;
        const int d0c  = ncol & 63;
        const float b0 = Bi[ncol];
        const float b1 = Bi[ncol + 1];
#pragma unroll
        for (int fi = 0; fi < 4; fi++) {
#pragma unroll
            for (int half = 0; half < 2; half++) {
                int m  = m0 + wm + fi * 16 + g + half * 8;
                int bi = m >> 11;
                int s  = m & (SEQ - 1);
                size_t off = ((size_t)(bi * NHEAD + h) * SEQ + s) * HDIM + d0c;
                uint16_t h0, l0, h1, l1;
                split2(D[fi][fj][half * 2 + 0] + b0, h0, l0);
                split2(D[fi][fj][half * 2 + 1] + b1, h1, l1);
                *(uint32_t*)(dh + off) = ((uint32_t)h1 << 16) | h0;
                *(uint32_t*)(dl + off) = ((uint32_t)l1 << 16) | l0;
            }
        }
    }
}

// ---------------------------------------------------------------------------
// v_kernel: V = X @ Wv + bv, SIMT fp32 (R10 path), epilogue -> bf16 hi/lo
// TRANSPOSED [bh][d][s].
// ---------------------------------------------------------------------------
__global__ __launch_bounds__(256) void v_kernel(
    const float* __restrict__ X,
    const float* __restrict__ Wv, const float* __restrict__ Bv)
{
    __shared__ float XsT[16][132];
    __shared__ float Ws[16][128];

    const int tid = threadIdx.x;
    const int tx  = tid & 15;
    const int ty  = tid >> 4;
    const int m0  = blockIdx.y * 128;
    const int n0  = blockIdx.x * 128;

    float acc[8][8];
#pragma unroll
    for (int i = 0; i < 8; i++)
#pragma unroll
        for (int j = 0; j < 8; j++) acc[i][j] = 0.f;

    for (int k0 = 0; k0 < HID; k0 += 16) {
#pragma unroll
        for (int p = 0; p < 2; p++) {
            int i  = tid + p * 256;
            int ml = i >> 2;
            int kq = i & 3;
            float4 v = *(const float4*)(X + (size_t)(m0 + ml) * HID + k0 + kq * 4);
            XsT[kq * 4 + 0][ml] = v.x;
            XsT[kq * 4 + 1][ml] = v.y;
            XsT[kq * 4 + 2][ml] = v.z;
            XsT[kq * 4 + 3][ml] = v.w;
        }
#pragma unroll
        for (int p = 0; p < 2; p++) {
            int i  = tid + p * 256;
            int kr = i >> 5;
            int nq = i & 31;
            float4 v = *(const float4*)(Wv + (size_t)(k0 + kr) * HID + n0 + nq * 4);
            *(float4*)&Ws[kr][nq * 4] = v;
        }
        __syncthreads();
#pragma unroll
        for (int kk = 0; kk < 16; kk++) {
            float4 a0 = *(const float4*)&XsT[kk][ty * 8];
            float4 a1 = *(const float4*)&XsT[kk][ty * 8 + 4];
            float4 b0 = *(const float4*)&Ws[kk][tx * 8];
            float4 b1 = *(const float4*)&Ws[kk][tx * 8 + 4];
            float a[8] = {a0.x, a0.y, a0.z, a0.w, a1.x, a1.y, a1.z, a1.w};
            float bb[8] = {b0.x, b0.y, b0.z, b0.w, b1.x, b1.y, b1.z, b1.w};
#pragma unroll
            for (int i = 0; i < 8; i++)
#pragma unroll
                for (int j = 0; j < 8; j++)
                    acc[i][j] = fmaf(a[i], bb[j], acc[i][j]);
        }
        __syncthreads();
    }

    const int ncol = n0 + tx * 8;
    const int h    = ncol >> 6;
    const int d0   = ncol & 63;
    float4 bA = *(const float4*)(Bv + ncol);
    float4 bB = *(const float4*)(Bv + ncol + 4);
    const float bb[8] = {bA.x, bA.y, bA.z, bA.w, bB.x, bB.y, bB.z, bB.w};

    const int mbase = m0 + ty * 8;
    const int bi = mbase >> 11;
    const int s0 = mbase & (SEQ - 1);
#pragma unroll
    for (int j = 0; j < 8; j++) {
        uint16_t hs[8], ls_[8];
#pragma unroll
        for (int i = 0; i < 8; i++)
            split2(acc[i][j] + bb[j], hs[i], ls_[i]);
        uint4 uh, ul;
        uint32_t* ph = (uint32_t*)&uh;
        uint32_t* pl = (uint32_t*)&ul;
#pragma unroll
        for (int w2 = 0; w2 < 4; w2++) {
            ph[w2] = ((uint32_t)hs[2 * w2 + 1] << 16) | hs[2 * w2];
            pl[w2] = ((uint32_t)ls_[2 * w2 + 1] << 16) | ls_[2 * w2];
        }
        size_t off = ((size_t)(bi * NHEAD + h) * HDIM + d0 + j) * SEQ + s0;
        *(uint4*)(g_vh + off) = uh;
        *(uint4*)(g_vl + off) = ul;
    }
}

// ---------------------------------------------------------------------------
// Kernel 2: flash attention (unchanged from round 10; 922us, tensor 41%).
// ---------------------------------------------------------------------------
__global__ __launch_bounds__(256) void attn_kernel(
    const int* __restrict__ mask,
    float* __restrict__ out)
{
    extern __shared__ char smraw[];
    __nv_bfloat16* Qh  = (__nv_bfloat16*)smraw;
    __nv_bfloat16* Ql  = (__nv_bfloat16*)(smraw + 18432);
    __nv_bfloat16* Kh  = (__nv_bfloat16*)(smraw + 36864);
    __nv_bfloat16* Kl  = (__nv_bfloat16*)(smraw + 55296);
    __nv_bfloat16* Ph  = (__nv_bfloat16*)(smraw + 36864);   // alias over Kh/Kl
    __nv_bfloat16* Pl  = (__nv_bfloat16*)(smraw + 71680);
    __nv_bfloat16* VhT = (__nv_bfloat16*)(smraw + 106496);
    __nv_bfloat16* VlT = (__nv_bfloat16*)(smraw + 123904);

    const int tid  = threadIdx.x;
    const int warp = tid >> 5;
    const int lane = tid & 31;
    const int g    = lane >> 2;
    const int t    = lane & 3;
    const int rlo  = warp * 16 + g;
    const int rhi  = rlo + 8;

    const int q0 = blockIdx.x * 128;
    const int bh = blockIdx.y;
    const int b  = bh >> 4;
    const int h  = bh & 15;

    const __nv_bfloat16* Qgh = g_qh + (size_t)bh * SEQ * HDIM;
    const __nv_bfloat16* Qgl = g_ql + (size_t)bh * SEQ * HDIM;
    const __nv_bfloat16* Kgh = g_kh + (size_t)bh * SEQ * HDIM;
    const __nv_bfloat16* Kgl = g_kl + (size_t)bh * SEQ * HDIM;
    const __nv_bfloat16* Vgh = g_vh + (size_t)bh * SEQ * HDIM;   // [d][s]
    const __nv_bfloat16* Vgl = g_vl + (size_t)bh * SEQ * HDIM;
    const int* __restrict__ mrow = mask + (size_t)b * SEQ;

#pragma unroll
    for (int p = 0; p < 4; p++) {
        int idx = tid + p * 256;
        int row = idx >> 3;
        int seg = idx & 7;
        uint4 vh = *(const uint4*)(Qgh + (size_t)(q0 + row) * HDIM + seg * 8);
        uint4 vl = *(const uint4*)(Qgl + (size_t)(q0 + row) * HDIM + seg * 8);
        *(uint4*)&Qh[row * 72 + seg * 8] = vh;
        *(uint4*)&Ql[row * 72 + seg * 8] = vl;
    }

    float acc[8][4];
#pragma unroll
    for (int f = 0; f < 8; f++)
#pragma unroll
        for (int e = 0; e < 4; e++) acc[f][e] = 0.f;
    float mpl = neg_inf_f(), mph = neg_inf_f();
    float lsl = 0.f, lsh = 0.f;

    for (int kt = 0; kt < SEQ / 128; kt++) {
        const int k0 = kt * 128;
        __syncthreads();

#pragma unroll
        for (int p = 0; p < 4; p++) {
            int idx = tid + p * 256;
            int row = idx >> 3;
            int seg = idx & 7;
            uint4 vh = *(const uint4*)(Kgh + (size_t)(k0 + row) * HDIM + seg * 8);
            uint4 vl = *(const uint4*)(Kgl + (size_t)(k0 + row) * HDIM + seg * 8);
            *(uint4*)&Kh[row * 72 + seg * 8] = vh;
            *(uint4*)&Kl[row * 72 + seg * 8] = vl;
        }
#pragma unroll
        for (int p = 0; p < 4; p++) {
            int idx = tid + p * 256;
            int row = idx >> 4;
            int seg = idx & 15;
            uint4 vh = *(const uint4*)(Vgh + (size_t)row * SEQ + k0 + seg * 8);
            uint4 vl = *(const uint4*)(Vgl + (size_t)row * SEQ + k0 + seg * 8);
            *(uint4*)&VhT[row * 136 + seg * 8] = vh;
            *(uint4*)&VlT[row * 136 + seg * 8] = vl;
        }
        __syncthreads();

        float s[16][4];
#pragma unroll
        for (int j = 0; j < 16; j++)
#pragma unroll
            for (int e = 0; e < 4; e++) s[j][e] = 0.f;

#pragma unroll
        for (int ks = 0; ks < 4; ks++) {
            const int kb = ks * 16 + 2 * t;
            uint32_t Ah[4], Al[4];
            Ah[0] = *(const uint32_t*)&Qh[rlo * 72 + kb];
            Ah[1] = *(const uint32_t*)&Qh[rhi * 72 + kb];
            Ah[2] = *(const uint32_t*)&Qh[rlo * 72 + kb + 8];
            Ah[3] = *(const uint32_t*)&Qh[rhi * 72 + kb + 8];
            Al[0] = *(const uint32_t*)&Ql[rlo * 72 + kb];
            Al[1] = *(const uint32_t*)&Ql[rhi * 72 + kb];
            Al[2] = *(const uint32_t*)&Ql[rlo * 72 + kb + 8];
            Al[3] = *(const uint32_t*)&Ql[rhi * 72 + kb + 8];
#pragma unroll
            for (int j = 0; j < 16; j++) {
                const int crow = 8 * j + g;
                uint32_t Bh[2], Bl[2];
                Bh[0] = *(const uint32_t*)&Kh[crow * 72 + kb];
                Bh[1] = *(const uint32_t*)&Kh[crow * 72 + kb + 8];
                Bl[0] = *(const uint32_t*)&Kl[crow * 72 + kb];
                Bl[1] = *(const uint32_t*)&Kl[crow * 72 + kb + 8];
                mma16816(s[j], Ah, Bh);
                mma16816(s[j], Ah, Bl);
                mma16816(s[j], Al, Bh);
            }
        }

        float mxl = neg_inf_f(), mxh = neg_inf_f();
#pragma unroll
        for (int j = 0; j < 16; j++) {
            float b0 = (mrow[k0 + 8 * j + 2 * t]     != 0) ? 0.f : NEG_F;
            float b1 = (mrow[k0 + 8 * j + 2 * t + 1] != 0) ? 0.f : NEG_F;
            s[j][0] = fmaf(s[j][0], 0.125f, b0);
            s[j][1] = fmaf(s[j][1], 0.125f, b1);
            s[j][2] = fmaf(s[j][2], 0.125f, b0);
            s[j][3] = fmaf(s[j][3], 0.125f, b1);
            mxl = fmaxf(mxl, fmaxf(s[j][0], s[j][1]));
            mxh = fmaxf(mxh, fmaxf(s[j][2], s[j][3]));
        }
        mxl = fmaxf(mxl, __shfl_xor_sync(0xffffffffu, mxl, 1));
        mxl = fmaxf(mxl, __shfl_xor_sync(0xffffffffu, mxl, 2));
        mxh = fmaxf(mxh, __shfl_xor_sync(0xffffffffu, mxh, 1));
        mxh = fmaxf(mxh, __shfl_xor_sync(0xffffffffu, mxh, 2));
        float mnl = fmaxf(mpl, mxl);
        float mnh = fmaxf(mph, mxh);
        float sfl = __expf(mpl - mnl);
        float sfh = __expf(mph - mnh);
        float rsl = 0.f, rsh = 0.f;
#pragma unroll
        for (int j = 0; j < 16; j++) {
            s[j][0] = __expf(s[j][0] - mnl); rsl += s[j][0];
            s[j][1] = __expf(s[j][1] - mnl); rsl += s[j][1];
            s[j][2] = __expf(s[j][2] - mnh); rsh += s[j][2];
            s[j][3] = __expf(s[j][3] - mnh); rsh += s[j][3];
        }
        rsl += __shfl_xor_sync(0xffffffffu, rsl, 1);
        rsl += __shfl_xor_sync(0xffffffffu, rsl, 2);
        rsh += __shfl_xor_sync(0xffffffffu, rsh, 1);
        rsh += __shfl_xor_sync(0xffffffffu, rsh, 2);
        lsl = lsl * sfl + rsl;
        lsh = lsh * sfh + rsh;
        mpl = mnl;
        mph = mnh;
        __syncthreads();

#pragma unroll
        for (int j = 0; j < 16; j++) {
            uint16_t h0, l0, h1, l1, h2, l2, h3, l3;
            split2(s[j][0], h0, l0);
            split2(s[j][1], h1, l1);
            split2(s[j][2], h2, l2);
            split2(s[j][3], h3, l3);
            *(uint32_t*)&Ph[rlo * 136 + 8 * j + 2 * t] = ((uint32_t)h1 << 16) | h0;
            *(uint32_t*)&Pl[rlo * 136 + 8 * j + 2 * t] = ((uint32_t)l1 << 16) | l0;
            *(uint32_t*)&Ph[rhi * 136 + 8 * j + 2 * t] = ((uint32_t)h3 << 16) | h2;
            *(uint32_t*)&Pl[rhi * 136 + 8 * j + 2 * t] = ((uint32_t)l3 << 16) | l2;
        }
        __syncthreads();

#pragma unroll
        for (int f = 0; f < 8; f++) {
            acc[f][0] *= sfl; acc[f][1] *= sfl;
            acc[f][2] *= sfh; acc[f][3] *= sfh;
        }
#pragma unroll
        for (int ks = 0; ks < 8; ks++) {
            const int kb = ks * 16 + 2 * t;
            uint32_t Ah[4], Al[4];
            Ah[0] = *(const uint32_t*)&Ph[rlo * 136 + kb];
            Ah[1] = *(const uint32_t*)&Ph[rhi * 136 + kb];
            Ah[2] = *(const uint32_t*)&Ph[rlo * 136 + kb + 8];
            Ah[3] = *(const uint32_t*)&Ph[rhi * 136 + kb + 8];
            Al[0] = *(const uint32_t*)&Pl[rlo * 136 + kb];
            Al[1] = *(const uint32_t*)&Pl[rhi * 136 + kb];
            Al[2] = *(const uint32_t*)&Pl[rlo * 136 + kb + 8];
            Al[3] = *(const uint32_t*)&Pl[rhi * 136 + kb + 8];
#pragma unroll
            for (int f = 0; f < 8; f++) {
                const int vr = 8 * f + g;
                uint32_t Bh[2], Bl[2];
                Bh[0] = *(const uint32_t*)&VhT[vr * 136 + kb];
                Bh[1] = *(const uint32_t*)&VhT[vr * 136 + kb + 8];
                Bl[0] = *(const uint32_t*)&VlT[vr * 136 + kb];
                Bl[1] = *(const uint32_t*)&VlT[vr * 136 + kb + 8];
                mma16816(acc[f], Ah, Bh);
                mma16816(acc[f], Ah, Bl);
                mma16816(acc[f], Al, Bh);
            }
        }
    }

    const float invl = 1.0f / lsl;
    const float invh = 1.0f / lsh;
    float* orow_lo = out + ((size_t)(b * SEQ + q0 + rlo)) * HID + h * HDIM;
    float* orow_hi = out + ((size_t)(b * SEQ + q0 + rhi)) * HID + h * HDIM;
#pragma unroll
    for (int f = 0; f < 8; f++) {
        int c = 8 * f + 2 * t;
        *(float2*)(orow_lo + c) = make_float2(acc[f][0] * invl, acc[f][1] * invl);
        *(float2*)(orow_hi + c) = make_float2(acc[f][2] * invh, acc[f][3] * invh);
    }
}

extern "C" void kernel_launch(void* const* d_in, const int* in_sizes, int n_in,
                              void* d_out, int out_size) {
    const float* X    = (const float*)d_in[0];
    const int*   mask = (const int*)d_in[1];
    const float* Wq   = (const float*)d_in[2];
    const float* Bq   = (const float*)d_in[3];
    const float* Wk   = (const float*)d_in[4];
    const float* Bk   = (const float*)d_in[5];
    const float* Wv   = (const float*)d_in[6];
    const float* Bv   = (const float*)d_in[7];
    float* out = (float*)d_out;

    split_x_kernel<<<MTOT * HID / 8 / 256, 256>>>(X);
    split_wt_kernel<<<dim3(HID / 32, HID / 32, 2), 256>>>(Wq, Wk);
    qk_kernel<<<dim3(HID / 128, MTOT / 128, 2), 256>>>(Bq, Bk);
    v_kernel<<<dim3(HID / 128, MTOT / 128, 1), 256>>>(X, Wv, Bv);

    static const int smem_bytes = 141312;
    cudaFuncSetAttribute(attn_kernel,
                         cudaFuncAttributeMaxDynamicSharedMemorySize, smem_bytes);
    dim3 g2(SEQ / 128, BATCH * NHEAD);
    attn_kernel<<<g2, 256, smem_bytes>>>(mask, out);
}

// round 12
// speedup vs baseline: 2.0335x; 1.1101x over previous
#include <cuda_runtime.h>
#include <cuda_bf16.h>
#include <cstdint>

#define BATCH 4
#define SEQ   2048
#define NHEAD 16
#define HDIM  64
#define HID   1024
#define NEG_F (-3.4028234663852886e38f)

#define NELT (BATCH * NHEAD * SEQ * HDIM)
#define MTOT (BATCH * SEQ)              // 8192 rows

// Scratch: Q/K bf16 hi/lo in [bh][s][d]; V bf16 hi/lo TRANSPOSED [bh][d][s].
__device__ __nv_bfloat16 g_qh[NELT];
__device__ __nv_bfloat16 g_ql[NELT];
__device__ __nv_bfloat16 g_kh[NELT];
__device__ __nv_bfloat16 g_kl[NELT];
__device__ __nv_bfloat16 g_vh[NELT];
__device__ __nv_bfloat16 g_vl[NELT];
// Pre-split X (hi/lo) and pre-split+transposed Wq/Wk/Wv ([n][k], z-major).
__device__ __nv_bfloat16 g_xh[MTOT * HID];
__device__ __nv_bfloat16 g_xl[MTOT * HID];
__device__ __nv_bfloat16 g_wth[3 * HID * HID];
__device__ __nv_bfloat16 g_wtl[3 * HID * HID];

__device__ __forceinline__ float neg_inf_f() { return __int_as_float(0xff800000); }

__device__ __forceinline__ void mma16816(float* d, const uint32_t* a, const uint32_t* b) {
    asm volatile(
        "mma.sync.aligned.m16n8k16.row.col.f32.bf16.bf16.f32 "
        "{%0,%1,%2,%3}, {%4,%5,%6,%7}, {%8,%9}, {%0,%1,%2,%3};"
        : "+f"(d[0]), "+f"(d[1]), "+f"(d[2]), "+f"(d[3])
        : "r"(a[0]), "r"(a[1]), "r"(a[2]), "r"(a[3]), "r"(b[0]), "r"(b[1]));
}

__device__ __forceinline__ void split2(float f, uint16_t& h, uint16_t& l) {
    __nv_bfloat16 hb = __float2bfloat16(f);
    __nv_bfloat16 lb = __float2bfloat16(f - __bfloat162float(hb));
    h = __bfloat16_as_ushort(hb);
    l = __bfloat16_as_ushort(lb);
}

// ---------------------------------------------------------------------------
// split_x: X fp32 -> g_xh/g_xl bf16.
// ---------------------------------------------------------------------------
__global__ __launch_bounds__(256) void split_x_kernel(const float* __restrict__ X) {
    int idx = blockIdx.x * 256 + threadIdx.x;     // 0 .. MTOT*HID/8 - 1
    const float4* xp = (const float4*)X;
    float4 a = xp[idx * 2];
    float4 c = xp[idx * 2 + 1];
    const float f[8] = {a.x, a.y, a.z, a.w, c.x, c.y, c.z, c.w};
    uint4 uh, ul;
    uint32_t* ph = (uint32_t*)&uh;
    uint32_t* pl = (uint32_t*)&ul;
#pragma unroll
    for (int j = 0; j < 4; j++) {
        uint16_t h0, l0, h1, l1;
        split2(f[2 * j],     h0, l0);
        split2(f[2 * j + 1], h1, l1);
        ph[j] = ((uint32_t)h1 << 16) | h0;
        pl[j] = ((uint32_t)l1 << 16) | l0;
    }
    *(uint4*)(g_xh + (size_t)idx * 8) = uh;
    *(uint4*)(g_xl + (size_t)idx * 8) = ul;
}

// ---------------------------------------------------------------------------
// split_wt: W[k][n] fp32 -> transposed bf16 hi/lo [n][k]. 32x32 smem tiles.
// z selects Wq (0) / Wk (1) / Wv (2).
// ---------------------------------------------------------------------------
__global__ __launch_bounds__(256) void split_wt_kernel(
    const float* __restrict__ Wq, const float* __restrict__ Wk,
    const float* __restrict__ Wv)
{
    __shared__ uint16_t shh[32 * 33];
    __shared__ uint16_t shl[32 * 33];
    const float* W = (blockIdx.z == 0) ? Wq : (blockIdx.z == 1) ? Wk : Wv;
    const size_t zoff = (size_t)blockIdx.z * HID * HID;
    const int k0 = blockIdx.y * 32;
    const int n0 = blockIdx.x * 32;
    const int tid = threadIdx.x;

#pragma unroll
    for (int p = 0; p < 4; p++) {
        int idx = tid + p * 256;        // 0..1023
        int kl = idx >> 5;              // 0..31
        int nl = idx & 31;
        float f = W[(size_t)(k0 + kl) * HID + n0 + nl];
        uint16_t h, l;
        split2(f, h, l);
        shh[nl * 33 + kl] = h;
        shl[nl * 33 + kl] = l;
    }
    __syncthreads();
#pragma unroll
    for (int p = 0; p < 2; p++) {
        int idx = tid + p * 256;        // 0..511
        int nl = idx >> 4;              // 0..31
        int kp = idx & 15;              // uint32 pair along k
        uint32_t vh = ((uint32_t)shh[nl * 33 + kp * 2 + 1] << 16) | shh[nl * 33 + kp * 2];
        uint32_t vl = ((uint32_t)shl[nl * 33 + kp * 2 + 1] << 16) | shl[nl * 33 + kp * 2];
        size_t off = zoff + (size_t)(n0 + nl) * HID + k0 + kp * 2;
        *(uint32_t*)(g_wth + off) = vh;
        *(uint32_t*)(g_wtl + off) = vl;
    }
}

// ---------------------------------------------------------------------------
// proj_kernel: Q/K/V projections via bf16x3-split mma (hh+hl+lh).
// BM=128, BN=128, BK=32. 8 warps (2m x 4n), warp 64x32, 4x4 m16n8k16 frags.
// Epilogue: z<2 -> [bh][s][d] hi/lo pairs (uint32 stores);
//           z==2 -> TRANSPOSED [bh][d][s] (scalar bf16 stores; lanes sharing
//           t cover 8 consecutive s -> 16B segments).
// ---------------------------------------------------------------------------
__global__ __launch_bounds__(256) void proj_kernel(
    const float* __restrict__ Bq, const float* __restrict__ Bk,
    const float* __restrict__ Bv)
{
    __shared__ __nv_bfloat16 Xhs[128 * 40];
    __shared__ __nv_bfloat16 Xls[128 * 40];
    __shared__ __nv_bfloat16 Whs[128 * 40];
    __shared__ __nv_bfloat16 Wls[128 * 40];

    const int z = blockIdx.z;
    const float* __restrict__ Bi = (z == 0) ? Bq : (z == 1) ? Bk : Bv;
    const __nv_bfloat16* Wth = g_wth + (size_t)z * HID * HID;
    const __nv_bfloat16* Wtl = g_wtl + (size_t)z * HID * HID;

    const int tid  = threadIdx.x;
    const int warp = tid >> 5;
    const int lane = tid & 31;
    const int g    = lane >> 2;
    const int t    = lane & 3;
    const int wm   = (warp >> 2) * 64;
    const int wn   = (warp & 3) * 32;
    const int m0   = blockIdx.y * 128;
    const int n0   = blockIdx.x * 128;

    float D[4][4][4];
#pragma unroll
    for (int fi = 0; fi < 4; fi++)
#pragma unroll
        for (int fj = 0; fj < 4; fj++)
#pragma unroll
            for (int e = 0; e < 4; e++) D[fi][fj][e] = 0.f;

    for (int k0 = 0; k0 < HID; k0 += 32) {
#pragma unroll
        for (int p = 0; p < 2; p++) {
            int idx = tid + p * 256;     // 0..511
            int row = idx >> 2;          // 0..127
            int seg = idx & 3;           // 4 x 8 bf16 = 32 k
            size_t xs = (size_t)(m0 + row) * HID + k0 + seg * 8;
            *(uint4*)&Xhs[row * 40 + seg * 8] = *(const uint4*)(g_xh + xs);
            *(uint4*)&Xls[row * 40 + seg * 8] = *(const uint4*)(g_xl + xs);
            size_t ws = (size_t)(n0 + row) * HID + k0 + seg * 8;
            *(uint4*)&Whs[row * 40 + seg * 8] = *(const uint4*)(Wth + ws);
            *(uint4*)&Wls[row * 40 + seg * 8] = *(const uint4*)(Wtl + ws);
        }
        __syncthreads();

#pragma unroll
        for (int ks = 0; ks < 2; ks++) {
            const int kb = ks * 16 + 2 * t;
            uint32_t Ah[4][4], Al[4][4];
#pragma unroll
            for (int fi = 0; fi < 4; fi++) {
                int r = wm + fi * 16 + g;
                Ah[fi][0] = *(const uint32_t*)&Xhs[r * 40 + kb];
                Ah[fi][1] = *(const uint32_t*)&Xhs[(r + 8) * 40 + kb];
                Ah[fi][2] = *(const uint32_t*)&Xhs[r * 40 + kb + 8];
                Ah[fi][3] = *(const uint32_t*)&Xhs[(r + 8) * 40 + kb + 8];
                Al[fi][0] = *(const uint32_t*)&Xls[r * 40 + kb];
                Al[fi][1] = *(const uint32_t*)&Xls[(r + 8) * 40 + kb];
                Al[fi][2] = *(const uint32_t*)&Xls[r * 40 + kb + 8];
                Al[fi][3] = *(const uint32_t*)&Xls[(r + 8) * 40 + kb + 8];
            }
#pragma unroll
            for (int fj = 0; fj < 4; fj++) {
                int c = wn + fj * 8 + g;
                uint32_t Bh[2], Bl[2];
                Bh[0] = *(const uint32_t*)&Whs[c * 40 + kb];
                Bh[1] = *(const uint32_t*)&Whs[c * 40 + kb + 8];
                Bl[0] = *(const uint32_t*)&Wls[c * 40 + kb];
                Bl[1] = *(const uint32_t*)&Wls[c * 40 + kb + 8];
#pragma unroll
                for (int fi = 0; fi < 4; fi++) {
                    mma16816(D[fi][fj], Ah[fi], Bh);
                    mma16816(D[fi][fj], Ah[fi], Bl);
                    mma16816(D[fi][fj], Al[fi], Bh);
                }
            }
        }
        __syncthreads();
    }

    if (z < 2) {
        __nv_bfloat16* dh = (z == 0) ? g_qh : g_kh;
        __nv_bfloat16* dl = (z == 0) ? g_ql : g_kl;
#pragma unroll
        for (int fj = 0; fj < 4; fj++) {
            const int ncol = n0 + wn + fj * 8 + 2 * t;
            const int h    = ncol >> 6;
            const int d0c  = ncol & 63;
            const float b0 = Bi[ncol];
            const float b1 = Bi[ncol + 1];
#pragma unroll
            for (int fi = 0; fi < 4; fi++) {
#pragma unroll
                for (int half = 0; half < 2; half++) {
                    int m  = m0 + wm + fi * 16 + g + half * 8;
                    int bi = m >> 11;
                    int s  = m & (SEQ - 1);
                    size_t off = ((size_t)(bi * NHEAD + h) * SEQ + s) * HDIM + d0c;
                    uint16_t h0, l0, h1, l1;
                    split2(D[fi][fj][half * 2 + 0] + b0, h0, l0);
                    split2(D[fi][fj][half * 2 + 1] + b1, h1, l1);
                    *(uint32_t*)(dh + off) = ((uint32_t)h1 << 16) | h0;
                    *(uint32_t*)(dl + off) = ((uint32_t)l1 << 16) | l0;
                }
            }
        }
    } else {
        // V: transposed [bh][d][s], scalar bf16 stores.
#pragma unroll
        for (int fj = 0; fj < 4; fj++) {
            const int ncol = n0 + wn + fj * 8 + 2 * t;
            const int h    = ncol >> 6;
            const int d0c  = ncol & 63;
            const float b0 = Bi[ncol];
            const float b1 = Bi[ncol + 1];
            const size_t dbase0 = ((size_t)h * HDIM + d0c) * SEQ;       // + bi*NHEAD*HDIM*SEQ
            const size_t dbase1 = ((size_t)h * HDIM + d0c + 1) * SEQ;
#pragma unroll
            for (int fi = 0; fi < 4; fi++) {
#pragma unroll
                for (int half = 0; half < 2; half++) {
                    int m  = m0 + wm + fi * 16 + g + half * 8;
                    int bi = m >> 11;
                    int s  = m & (SEQ - 1);
                    size_t boff = (size_t)bi * NHEAD * HDIM * SEQ;
                    uint16_t h0, l0, h1, l1;
                    split2(D[fi][fj][half * 2 + 0] + b0, h0, l0);
                    split2(D[fi][fj][half * 2 + 1] + b1, h1, l1);
                    ((uint16_t*)g_vh)[boff + dbase0 + s] = h0;
                    ((uint16_t*)g_vl)[boff + dbase0 + s] = l0;
                    ((uint16_t*)g_vh)[boff + dbase1 + s] = h1;
                    ((uint16_t*)g_vl)[boff + dbase1 + s] = l1;
                }
            }
        }
    }
}

// ---------------------------------------------------------------------------
// Kernel 2: flash attention (unchanged from round 10; 922us, tensor 41%).
// ---------------------------------------------------------------------------
__global__ __launch_bounds__(256) void attn_kernel(
    const int* __restrict__ mask,
    float* __restrict__ out)
{
    extern __shared__ char smraw[];
    __nv_bfloat16* Qh  = (__nv_bfloat16*)smraw;
    __nv_bfloat16* Ql  = (__nv_bfloat16*)(smraw + 18432);
    __nv_bfloat16* Kh  = (__nv_bfloat16*)(smraw + 36864);
    __nv_bfloat16* Kl  = (__nv_bfloat16*)(smraw + 55296);
    __nv_bfloat16* Ph  = (__nv_bfloat16*)(smraw + 36864);   // alias over Kh/Kl
    __nv_bfloat16* Pl  = (__nv_bfloat16*)(smraw + 71680);
    __nv_bfloat16* VhT = (__nv_bfloat16*)(smraw + 106496);
    __nv_bfloat16* VlT = (__nv_bfloat16*)(smraw + 123904);

    const int tid  = threadIdx.x;
    const int warp = tid >> 5;
    const int lane = tid & 31;
    const int g    = lane >> 2;
    const int t    = lane & 3;
    const int rlo  = warp * 16 + g;
    const int rhi  = rlo + 8;

    const int q0 = blockIdx.x * 128;
    const int bh = blockIdx.y;
    const int b  = bh >> 4;
    const int h  = bh & 15;

    const __nv_bfloat16* Qgh = g_qh + (size_t)bh * SEQ * HDIM;
    const __nv_bfloat16* Qgl = g_ql + (size_t)bh * SEQ * HDIM;
    const __nv_bfloat16* Kgh = g_kh + (size_t)bh * SEQ * HDIM;
    const __nv_bfloat16* Kgl = g_kl + (size_t)bh * SEQ * HDIM;
    const __nv_bfloat16* Vgh = g_vh + (size_t)bh * SEQ * HDIM;   // [d][s]
    const __nv_bfloat16* Vgl = g_vl + (size_t)bh * SEQ * HDIM;
    const int* __restrict__ mrow = mask + (size_t)b * SEQ;

#pragma unroll
    for (int p = 0; p < 4; p++) {
        int idx = tid + p * 256;
        int row = idx >> 3;
        int seg = idx & 7;
        uint4 vh = *(const uint4*)(Qgh + (size_t)(q0 + row) * HDIM + seg * 8);
        uint4 vl = *(const uint4*)(Qgl + (size_t)(q0 + row) * HDIM + seg * 8);
        *(uint4*)&Qh[row * 72 + seg * 8] = vh;
        *(uint4*)&Ql[row * 72 + seg * 8] = vl;
    }

    float acc[8][4];
#pragma unroll
    for (int f = 0; f < 8; f++)
#pragma unroll
        for (int e = 0; e < 4; e++) acc[f][e] = 0.f;
    float mpl = neg_inf_f(), mph = neg_inf_f();
    float lsl = 0.f, lsh = 0.f;

    for (int kt = 0; kt < SEQ / 128; kt++) {
        const int k0 = kt * 128;
        __syncthreads();

#pragma unroll
        for (int p = 0; p < 4; p++) {
            int idx = tid + p * 256;
            int row = idx >> 3;
            int seg = idx & 7;
            uint4 vh = *(const uint4*)(Kgh + (size_t)(k0 + row) * HDIM + seg * 8);
            uint4 vl = *(const uint4*)(Kgl + (size_t)(k0 + row) * HDIM + seg * 8);
            *(uint4*)&Kh[row * 72 + seg * 8] = vh;
            *(uint4*)&Kl[row * 72 + seg * 8] = vl;
        }
#pragma unroll
        for (int p = 0; p < 4; p++) {
            int idx = tid + p * 256;
            int row = idx >> 4;
            int seg = idx & 15;
            uint4 vh = *(const uint4*)(Vgh + (size_t)row * SEQ + k0 + seg * 8);
            uint4 vl = *(const uint4*)(Vgl + (size_t)row * SEQ + k0 + seg * 8);
            *(uint4*)&VhT[row * 136 + seg * 8] = vh;
            *(uint4*)&VlT[row * 136 + seg * 8] = vl;
        }
        __syncthreads();

        float s[16][4];
#pragma unroll
        for (int j = 0; j < 16; j++)
#pragma unroll
            for (int e = 0; e < 4; e++) s[j][e] = 0.f;

#pragma unroll
        for (int ks = 0; ks < 4; ks++) {
            const int kb = ks * 16 + 2 * t;
            uint32_t Ah[4], Al[4];
            Ah[0] = *(const uint32_t*)&Qh[rlo * 72 + kb];
            Ah[1] = *(const uint32_t*)&Qh[rhi * 72 + kb];
            Ah[2] = *(const uint32_t*)&Qh[rlo * 72 + kb + 8];
            Ah[3] = *(const uint32_t*)&Qh[rhi * 72 + kb + 8];
            Al[0] = *(const uint32_t*)&Ql[rlo * 72 + kb];
            Al[1] = *(const uint32_t*)&Ql[rhi * 72 + kb];
            Al[2] = *(const uint32_t*)&Ql[rlo * 72 + kb + 8];
            Al[3] = *(const uint32_t*)&Ql[rhi * 72 + kb + 8];
#pragma unroll
            for (int j = 0; j < 16; j++) {
                const int crow = 8 * j + g;
                uint32_t Bh[2], Bl[2];
                Bh[0] = *(const uint32_t*)&Kh[crow * 72 + kb];
                Bh[1] = *(const uint32_t*)&Kh[crow * 72 + kb + 8];
                Bl[0] = *(const uint32_t*)&Kl[crow * 72 + kb];
                Bl[1] = *(const uint32_t*)&Kl[crow * 72 + kb + 8];
                mma16816(s[j], Ah, Bh);
                mma16816(s[j], Ah, Bl);
                mma16816(s[j], Al, Bh);
            }
        }

        float mxl = neg_inf_f(), mxh = neg_inf_f();
#pragma unroll
        for (int j = 0; j < 16; j++) {
            float b0 = (mrow[k0 + 8 * j + 2 * t]     != 0) ? 0.f : NEG_F;
            float b1 = (mrow[k0 + 8 * j + 2 * t + 1] != 0) ? 0.f : NEG_F;
            s[j][0] = fmaf(s[j][0], 0.125f, b0);
            s[j][1] = fmaf(s[j][1], 0.125f, b1);
            s[j][2] = fmaf(s[j][2], 0.125f, b0);
            s[j][3] = fmaf(s[j][3], 0.125f, b1);
            mxl = fmaxf(mxl, fmaxf(s[j][0], s[j][1]));
            mxh = fmaxf(mxh, fmaxf(s[j][2], s[j][3]));
        }
        mxl = fmaxf(mxl, __shfl_xor_sync(0xffffffffu, mxl, 1));
        mxl = fmaxf(mxl, __shfl_xor_sync(0xffffffffu, mxl, 2));
        mxh = fmaxf(mxh, __shfl_xor_sync(0xffffffffu, mxh, 1));
        mxh = fmaxf(mxh, __shfl_xor_sync(0xffffffffu, mxh, 2));
        float mnl = fmaxf(mpl, mxl);
        float mnh = fmaxf(mph, mxh);
        float sfl = __expf(mpl - mnl);
        float sfh = __expf(mph - mnh);
        float rsl = 0.f, rsh = 0.f;
#pragma unroll
        for (int j = 0; j < 16; j++) {
            s[j][0] = __expf(s[j][0] - mnl); rsl += s[j][0];
            s[j][1] = __expf(s[j][1] - mnl); rsl += s[j][1];
            s[j][2] = __expf(s[j][2] - mnh); rsh += s[j][2];
            s[j][3] = __expf(s[j][3] - mnh); rsh += s[j][3];
        }
        rsl += __shfl_xor_sync(0xffffffffu, rsl, 1);
        rsl += __shfl_xor_sync(0xffffffffu, rsl, 2);
        rsh += __shfl_xor_sync(0xffffffffu, rsh, 1);
        rsh += __shfl_xor_sync(0xffffffffu, rsh, 2);
        lsl = lsl * sfl + rsl;
        lsh = lsh * sfh + rsh;
        mpl = mnl;
        mph = mnh;
        __syncthreads();

#pragma unroll
        for (int j = 0; j < 16; j++) {
            uint16_t h0, l0, h1, l1, h2, l2, h3, l3;
            split2(s[j][0], h0, l0);
            split2(s[j][1], h1, l1);
            split2(s[j][2], h2, l2);
            split2(s[j][3], h3, l3);
            *(uint32_t*)&Ph[rlo * 136 + 8 * j + 2 * t] = ((uint32_t)h1 << 16) | h0;
            *(uint32_t*)&Pl[rlo * 136 + 8 * j + 2 * t] = ((uint32_t)l1 << 16) | l0;
            *(uint32_t*)&Ph[rhi * 136 + 8 * j + 2 * t] = ((uint32_t)h3 << 16) | h2;
            *(uint32_t*)&Pl[rhi * 136 + 8 * j + 2 * t] = ((uint32_t)l3 << 16) | l2;
        }
        __syncthreads();

#pragma unroll
        for (int f = 0; f < 8; f++) {
            acc[f][0] *= sfl; acc[f][1] *= sfl;
            acc[f][2] *= sfh; acc[f][3] *= sfh;
        }
#pragma unroll
        for (int ks = 0; ks < 8; ks++) {
            const int kb = ks * 16 + 2 * t;
            uint32_t Ah[4], Al[4];
            Ah[0] = *(const uint32_t*)&Ph[rlo * 136 + kb];
            Ah[1] = *(const uint32_t*)&Ph[rhi * 136 + kb];
            Ah[2] = *(const uint32_t*)&Ph[rlo * 136 + kb + 8];
            Ah[3] = *(const uint32_t*)&Ph[rhi * 136 + kb + 8];
            Al[0] = *(const uint32_t*)&Pl[rlo * 136 + kb];
            Al[1] = *(const uint32_t*)&Pl[rhi * 136 + kb];
            Al[2] = *(const uint32_t*)&Pl[rlo * 136 + kb + 8];
            Al[3] = *(const uint32_t*)&Pl[rhi * 136 + kb + 8];
#pragma unroll
            for (int f = 0; f < 8; f++) {
                const int vr = 8 * f + g;
                uint32_t Bh[2], Bl[2];
                Bh[0] = *(const uint32_t*)&VhT[vr * 136 + kb];
                Bh[1] = *(const uint32_t*)&VhT[vr * 136 + kb + 8];
                Bl[0] = *(const uint32_t*)&VlT[vr * 136 + kb];
                Bl[1] = *(const uint32_t*)&VlT[vr * 136 + kb + 8];
                mma16816(acc[f], Ah, Bh);
                mma16816(acc[f], Ah, Bl);
                mma16816(acc[f], Al, Bh);
            }
        }
    }

    const float invl = 1.0f / lsl;
    const float invh = 1.0f / lsh;
    float* orow_lo = out + ((size_t)(b * SEQ + q0 + rlo)) * HID + h * HDIM;
    float* orow_hi = out + ((size_t)(b * SEQ + q0 + rhi)) * HID + h * HDIM;
#pragma unroll
    for (int f = 0; f < 8; f++) {
        int c = 8 * f + 2 * t;
        *(float2*)(orow_lo + c) = make_float2(acc[f][0] * invl, acc[f][1] * invl);
        *(float2*)(orow_hi + c) = make_float2(acc[f][2] * invh, acc[f][3] * invh);
    }
}

extern "C" void kernel_launch(void* const* d_in, const int* in_sizes, int n_in,
                              void* d_out, int out_size) {
    const float* X    = (const float*)d_in[0];
    const int*   mask = (const int*)d_in[1];
    const float* Wq   = (const float*)d_in[2];
    const float* Bq   = (const float*)d_in[3];
    const float* Wk   = (const float*)d_in[4];
    const float* Bk   = (const float*)d_in[5];
    const float* Wv   = (const float*)d_in[6];
    const float* Bv   = (const float*)d_in[7];
    float* out = (float*)d_out;

    split_x_kernel<<<MTOT * HID / 8 / 256, 256>>>(X);
    split_wt_kernel<<<dim3(HID / 32, HID / 32, 3), 256>>>(Wq, Wk, Wv);
    proj_kernel<<<dim3(HID / 128, MTOT / 128, 3), 256>>>(Bq, Bk, Bv);

    static const int smem_bytes = 141312;
    cudaFuncSetAttribute(attn_kernel,
                         cudaFuncAttributeMaxDynamicSharedMemorySize, smem_bytes);
    dim3 g2(SEQ / 128, BATCH * NHEAD);
    attn_kernel<<<g2, 256, smem_bytes>>>(mask, out);
}

// round 14
// speedup vs baseline: 2.3367x; 1.1491x over previous
#include <cuda_runtime.h>
#include <cuda_bf16.h>
#include <cstdint>

#define BATCH 4
#define SEQ   2048
#define NHEAD 16
#define HDIM  64
#define HID   1024
#define NEG_F (-3.4028234663852886e38f)

#define NELT (BATCH * NHEAD * SEQ * HDIM)
#define MTOT (BATCH * SEQ)              // 8192 rows

// Scratch: Q/K bf16 hi/lo in [bh][s][d]; V bf16 hi/lo TRANSPOSED [bh][d][s].
__device__ __nv_bfloat16 g_qh[NELT];
__device__ __nv_bfloat16 g_ql[NELT];
__device__ __nv_bfloat16 g_kh[NELT];
__device__ __nv_bfloat16 g_kl[NELT];
__device__ __nv_bfloat16 g_vh[NELT];
__device__ __nv_bfloat16 g_vl[NELT];
// Pre-split X (hi/lo) and pre-split+transposed Wq/Wk/Wv ([n][k], z-major).
__device__ __nv_bfloat16 g_xh[MTOT * HID];
__device__ __nv_bfloat16 g_xl[MTOT * HID];
__device__ __nv_bfloat16 g_wth[3 * HID * HID];
__device__ __nv_bfloat16 g_wtl[3 * HID * HID];

__device__ __forceinline__ float neg_inf_f() { return __int_as_float(0xff800000); }

__device__ __forceinline__ void mma16816(float* d, const uint32_t* a, const uint32_t* b) {
    asm volatile(
        "mma.sync.aligned.m16n8k16.row.col.f32.bf16.bf16.f32 "
        "{%0,%1,%2,%3}, {%4,%5,%6,%7}, {%8,%9}, {%0,%1,%2,%3};"
        : "+f"(d[0]), "+f"(d[1]), "+f"(d[2]), "+f"(d[3])
        : "r"(a[0]), "r"(a[1]), "r"(a[2]), "r"(a[3]), "r"(b[0]), "r"(b[1]));
}

__device__ __forceinline__ void split2(float f, uint16_t& h, uint16_t& l) {
    __nv_bfloat16 hb = __float2bfloat16(f);
    __nv_bfloat16 lb = __float2bfloat16(f - __bfloat162float(hb));
    h = __bfloat16_as_ushort(hb);
    l = __bfloat16_as_ushort(lb);
}

// Split a float pair into packed bf16 hi-pair and lo-pair.
__device__ __forceinline__ void splitpack(float f0, float f1, uint32_t& ph, uint32_t& pl) {
    uint16_t h0, l0, h1, l1;
    split2(f0, h0, l0);
    split2(f1, h1, l1);
    ph = ((uint32_t)h1 << 16) | h0;
    pl = ((uint32_t)l1 << 16) | l0;
}

// ---------------------------------------------------------------------------
// split_x: X fp32 -> g_xh/g_xl bf16.
// ---------------------------------------------------------------------------
__global__ __launch_bounds__(256) void split_x_kernel(const float* __restrict__ X) {
    int idx = blockIdx.x * 256 + threadIdx.x;     // 0 .. MTOT*HID/8 - 1
    const float4* xp = (const float4*)X;
    float4 a = xp[idx * 2];
    float4 c = xp[idx * 2 + 1];
    const float f[8] = {a.x, a.y, a.z, a.w, c.x, c.y, c.z, c.w};
    uint4 uh, ul;
    uint32_t* ph = (uint32_t*)&uh;
    uint32_t* pl = (uint32_t*)&ul;
#pragma unroll
    for (int j = 0; j < 4; j++)
        splitpack(f[2 * j], f[2 * j + 1], ph[j], pl[j]);
    *(uint4*)(g_xh + (size_t)idx * 8) = uh;
    *(uint4*)(g_xl + (size_t)idx * 8) = ul;
}

// ---------------------------------------------------------------------------
// split_wt: W[k][n] fp32 -> transposed bf16 hi/lo [n][k]. 32x32 smem tiles.
// ---------------------------------------------------------------------------
__global__ __launch_bounds__(256) void split_wt_kernel(
    const float* __restrict__ Wq, const float* __restrict__ Wk,
    const float* __restrict__ Wv)
{
    __shared__ uint16_t shh[32 * 33];
    __shared__ uint16_t shl[32 * 33];
    const float* W = (blockIdx.z == 0) ? Wq : (blockIdx.z == 1) ? Wk : Wv;
    const size_t zoff = (size_t)blockIdx.z * HID * HID;
    const int k0 = blockIdx.y * 32;
    const int n0 = blockIdx.x * 32;
    const int tid = threadIdx.x;

#pragma unroll
    for (int p = 0; p < 4; p++) {
        int idx = tid + p * 256;
        int kl = idx >> 5;
        int nl = idx & 31;
        float f = W[(size_t)(k0 + kl) * HID + n0 + nl];
        uint16_t h, l;
        split2(f, h, l);
        shh[nl * 33 + kl] = h;
        shl[nl * 33 + kl] = l;
    }
    __syncthreads();
#pragma unroll
    for (int p = 0; p < 2; p++) {
        int idx = tid + p * 256;
        int nl = idx >> 4;
        int kp = idx & 15;
        uint32_t vh = ((uint32_t)shh[nl * 33 + kp * 2 + 1] << 16) | shh[nl * 33 + kp * 2];
        uint32_t vl = ((uint32_t)shl[nl * 33 + kp * 2 + 1] << 16) | shl[nl * 33 + kp * 2];
        size_t off = zoff + (size_t)(n0 + nl) * HID + k0 + kp * 2;
        *(uint32_t*)(g_wth + off) = vh;
        *(uint32_t*)(g_wtl + off) = vl;
    }
}

// ---------------------------------------------------------------------------
// proj_kernel: Q/K/V projections via bf16x3-split mma (unchanged from R12).
// ---------------------------------------------------------------------------
__global__ __launch_bounds__(256) void proj_kernel(
    const float* __restrict__ Bq, const float* __restrict__ Bk,
    const float* __restrict__ Bv)
{
    __shared__ __nv_bfloat16 Xhs[128 * 40];
    __shared__ __nv_bfloat16 Xls[128 * 40];
    __shared__ __nv_bfloat16 Whs[128 * 40];
    __shared__ __nv_bfloat16 Wls[128 * 40];

    const int z = blockIdx.z;
    const float* __restrict__ Bi = (z == 0) ? Bq : (z == 1) ? Bk : Bv;
    const __nv_bfloat16* Wth = g_wth + (size_t)z * HID * HID;
    const __nv_bfloat16* Wtl = g_wtl + (size_t)z * HID * HID;

    const int tid  = threadIdx.x;
    const int warp = tid >> 5;
    const int lane = tid & 31;
    const int g    = lane >> 2;
    const int t    = lane & 3;
    const int wm   = (warp >> 2) * 64;
    const int wn   = (warp & 3) * 32;
    const int m0   = blockIdx.y * 128;
    const int n0   = blockIdx.x * 128;

    float D[4][4][4];
#pragma unroll
    for (int fi = 0; fi < 4; fi++)
#pragma unroll
        for (int fj = 0; fj < 4; fj++)
#pragma unroll
            for (int e = 0; e < 4; e++) D[fi][fj][e] = 0.f;

    for (int k0 = 0; k0 < HID; k0 += 32) {
#pragma unroll
        for (int p = 0; p < 2; p++) {
            int idx = tid + p * 256;
            int row = idx >> 2;
            int seg = idx & 3;
            size_t xs = (size_t)(m0 + row) * HID + k0 + seg * 8;
            *(uint4*)&Xhs[row * 40 + seg * 8] = *(const uint4*)(g_xh + xs);
            *(uint4*)&Xls[row * 40 + seg * 8] = *(const uint4*)(g_xl + xs);
            size_t ws = (size_t)(n0 + row) * HID + k0 + seg * 8;
            *(uint4*)&Whs[row * 40 + seg * 8] = *(const uint4*)(Wth + ws);
            *(uint4*)&Wls[row * 40 + seg * 8] = *(const uint4*)(Wtl + ws);
        }
        __syncthreads();

#pragma unroll
        for (int ks = 0; ks < 2; ks++) {
            const int kb = ks * 16 + 2 * t;
            uint32_t Ah[4][4], Al[4][4];
#pragma unroll
            for (int fi = 0; fi < 4; fi++) {
                int r = wm + fi * 16 + g;
                Ah[fi][0] = *(const uint32_t*)&Xhs[r * 40 + kb];
                Ah[fi][1] = *(const uint32_t*)&Xhs[(r + 8) * 40 + kb];
                Ah[fi][2] = *(const uint32_t*)&Xhs[r * 40 + kb + 8];
                Ah[fi][3] = *(const uint32_t*)&Xhs[(r + 8) * 40 + kb + 8];
                Al[fi][0] = *(const uint32_t*)&Xls[r * 40 + kb];
                Al[fi][1] = *(const uint32_t*)&Xls[(r + 8) * 40 + kb];
                Al[fi][2] = *(const uint32_t*)&Xls[r * 40 + kb + 8];
                Al[fi][3] = *(const uint32_t*)&Xls[(r + 8) * 40 + kb + 8];
            }
#pragma unroll
            for (int fj = 0; fj < 4; fj++) {
                int c = wn + fj * 8 + g;
                uint32_t Bh[2], Bl[2];
                Bh[0] = *(const uint32_t*)&Whs[c * 40 + kb];
                Bh[1] = *(const uint32_t*)&Whs[c * 40 + kb + 8];
                Bl[0] = *(const uint32_t*)&Wls[c * 40 + kb];
                Bl[1] = *(const uint32_t*)&Wls[c * 40 + kb + 8];
#pragma unroll
                for (int fi = 0; fi < 4; fi++) {
                    mma16816(D[fi][fj], Ah[fi], Bh);
                    mma16816(D[fi][fj], Ah[fi], Bl);
                    mma16816(D[fi][fj], Al[fi], Bh);
                }
            }
        }
        __syncthreads();
    }

    if (z < 2) {
        __nv_bfloat16* dh = (z == 0) ? g_qh : g_kh;
        __nv_bfloat16* dl = (z == 0) ? g_ql : g_kl;
#pragma unroll
        for (int fj = 0; fj < 4; fj++) {
            const int ncol = n0 + wn + fj * 8 + 2 * t;
            const int h    = ncol >> 6;
            const int d0c  = ncol & 63;
            const float b0 = Bi[ncol];
            const float b1 = Bi[ncol + 1];
#pragma unroll
            for (int fi = 0; fi < 4; fi++) {
#pragma unroll
                for (int half = 0; half < 2; half++) {
                    int m  = m0 + wm + fi * 16 + g + half * 8;
                    int bi = m >> 11;
                    int s  = m & (SEQ - 1);
                    size_t off = ((size_t)(bi * NHEAD + h) * SEQ + s) * HDIM + d0c;
                    uint32_t ph, pl;
                    splitpack(D[fi][fj][half * 2 + 0] + b0,
                              D[fi][fj][half * 2 + 1] + b1, ph, pl);
                    *(uint32_t*)(dh + off) = ph;
                    *(uint32_t*)(dl + off) = pl;
                }
            }
        }
    } else {
        // V: transposed [bh][d][s], scalar bf16 stores.
#pragma unroll
        for (int fj = 0; fj < 4; fj++) {
            const int ncol = n0 + wn + fj * 8 + 2 * t;
            const int h    = ncol >> 6;
            const int d0c  = ncol & 63;
            const float b0 = Bi[ncol];
            const float b1 = Bi[ncol + 1];
            const size_t dbase0 = ((size_t)h * HDIM + d0c) * SEQ;
            const size_t dbase1 = ((size_t)h * HDIM + d0c + 1) * SEQ;
#pragma unroll
            for (int fi = 0; fi < 4; fi++) {
#pragma unroll
                for (int half = 0; half < 2; half++) {
                    int m  = m0 + wm + fi * 16 + g + half * 8;
                    int bi = m >> 11;
                    int s  = m & (SEQ - 1);
                    size_t boff = (size_t)bi * NHEAD * HDIM * SEQ;
                    uint16_t h0, l0, h1, l1;
                    split2(D[fi][fj][half * 2 + 0] + b0, h0, l0);
                    split2(D[fi][fj][half * 2 + 1] + b1, h1, l1);
                    ((uint16_t*)g_vh)[boff + dbase0 + s] = h0;
                    ((uint16_t*)g_vl)[boff + dbase0 + s] = l0;
                    ((uint16_t*)g_vh)[boff + dbase1 + s] = h1;
                    ((uint16_t*)g_vl)[boff + dbase1 + s] = l1;
                }
            }
        }
    }
}

// ---------------------------------------------------------------------------
// Kernel 2: flash attention, BQ=128 x BK=128, 256 threads, 2 CTAs/SM.
// S and PV both bf16x3-split mma. P stays IN REGISTERS: the softmax'd S
// C-fragments are exactly the PV A-fragments (a0..a3 = s[2ks][0..3],
// s[2ks+1][0..3]); split to hi/lo on the fly. No P smem, 2 syncs/tile.
// Smem (dynamic, 108544 B -> 2 CTAs/SM):
//   Qh @0, Ql @18432  (bf16[128][72])
//   Kh @36864, Kl @55296 (bf16[128][72])
//   VhT @73728, VlT @91136 (bf16[64][136], V^T [d][k])
// ---------------------------------------------------------------------------
__global__ __launch_bounds__(256, 2) void attn_kernel(
    const int* __restrict__ mask,
    float* __restrict__ out)
{
    extern __shared__ char smraw[];
    __nv_bfloat16* Qh  = (__nv_bfloat16*)smraw;
    __nv_bfloat16* Ql  = (__nv_bfloat16*)(smraw + 18432);
    __nv_bfloat16* Kh  = (__nv_bfloat16*)(smraw + 36864);
    __nv_bfloat16* Kl  = (__nv_bfloat16*)(smraw + 55296);
    __nv_bfloat16* VhT = (__nv_bfloat16*)(smraw + 73728);
    __nv_bfloat16* VlT = (__nv_bfloat16*)(smraw + 91136);

    const int tid  = threadIdx.x;
    const int warp = tid >> 5;
    const int lane = tid & 31;
    const int g    = lane >> 2;
    const int t    = lane & 3;
    const int rlo  = warp * 16 + g;
    const int rhi  = rlo + 8;

    const int q0 = blockIdx.x * 128;
    const int bh = blockIdx.y;
    const int b  = bh >> 4;
    const int h  = bh & 15;

    const __nv_bfloat16* Qgh = g_qh + (size_t)bh * SEQ * HDIM;
    const __nv_bfloat16* Qgl = g_ql + (size_t)bh * SEQ * HDIM;
    const __nv_bfloat16* Kgh = g_kh + (size_t)bh * SEQ * HDIM;
    const __nv_bfloat16* Kgl = g_kl + (size_t)bh * SEQ * HDIM;
    const __nv_bfloat16* Vgh = g_vh + (size_t)bh * SEQ * HDIM;   // [d][s]
    const __nv_bfloat16* Vgl = g_vl + (size_t)bh * SEQ * HDIM;
    const int* __restrict__ mrow = mask + (size_t)b * SEQ;

#pragma unroll
    for (int p = 0; p < 4; p++) {
        int idx = tid + p * 256;
        int row = idx >> 3;
        int seg = idx & 7;
        uint4 vh = *(const uint4*)(Qgh + (size_t)(q0 + row) * HDIM + seg * 8);
        uint4 vl = *(const uint4*)(Qgl + (size_t)(q0 + row) * HDIM + seg * 8);
        *(uint4*)&Qh[row * 72 + seg * 8] = vh;
        *(uint4*)&Ql[row * 72 + seg * 8] = vl;
    }

    float acc[8][4];
#pragma unroll
    for (int f = 0; f < 8; f++)
#pragma unroll
        for (int e = 0; e < 4; e++) acc[f][e] = 0.f;
    float mpl = neg_inf_f(), mph = neg_inf_f();
    float lsl = 0.f, lsh = 0.f;

    for (int kt = 0; kt < SEQ / 128; kt++) {
        const int k0 = kt * 128;
        __syncthreads();   // prev tile's K/V smem reads done; (iter 0) Q visible

#pragma unroll
        for (int p = 0; p < 4; p++) {
            int idx = tid + p * 256;
            int row = idx >> 3;
            int seg = idx & 7;
            uint4 vh = *(const uint4*)(Kgh + (size_t)(k0 + row) * HDIM + seg * 8);
            uint4 vl = *(const uint4*)(Kgl + (size_t)(k0 + row) * HDIM + seg * 8);
            *(uint4*)&Kh[row * 72 + seg * 8] = vh;
            *(uint4*)&Kl[row * 72 + seg * 8] = vl;
        }
#pragma unroll
        for (int p = 0; p < 4; p++) {
            int idx = tid + p * 256;
            int row = idx >> 4;
            int seg = idx & 15;
            uint4 vh = *(const uint4*)(Vgh + (size_t)row * SEQ + k0 + seg * 8);
            uint4 vl = *(const uint4*)(Vgl + (size_t)row * SEQ + k0 + seg * 8);
            *(uint4*)&VhT[row * 136 + seg * 8] = vh;
            *(uint4*)&VlT[row * 136 + seg * 8] = vl;
        }
        __syncthreads();

        // ---- S = Q K^T (3-term split mma) ----
        float s[16][4];
#pragma unroll
        for (int j = 0; j < 16; j++)
#pragma unroll
            for (int e = 0; e < 4; e++) s[j][e] = 0.f;

#pragma unroll
        for (int ks = 0; ks < 4; ks++) {
            const int kb = ks * 16 + 2 * t;
            uint32_t Ah[4], Al[4];
            Ah[0] = *(const uint32_t*)&Qh[rlo * 72 + kb];
            Ah[1] = *(const uint32_t*)&Qh[rhi * 72 + kb];
            Ah[2] = *(const uint32_t*)&Qh[rlo * 72 + kb + 8];
            Ah[3] = *(const uint32_t*)&Qh[rhi * 72 + kb + 8];
            Al[0] = *(const uint32_t*)&Ql[rlo * 72 + kb];
            Al[1] = *(const uint32_t*)&Ql[rhi * 72 + kb];
            Al[2] = *(const uint32_t*)&Ql[rlo * 72 + kb + 8];
            Al[3] = *(const uint32_t*)&Ql[rhi * 72 + kb + 8];
#pragma unroll
            for (int j = 0; j < 16; j++) {
                const int crow = 8 * j + g;
                uint32_t Bh[2], Bl[2];
                Bh[0] = *(const uint32_t*)&Kh[crow * 72 + kb];
                Bh[1] = *(const uint32_t*)&Kh[crow * 72 + kb + 8];
                Bl[0] = *(const uint32_t*)&Kl[crow * 72 + kb];
                Bl[1] = *(const uint32_t*)&Kl[crow * 72 + kb + 8];
                mma16816(s[j], Ah, Bh);
                mma16816(s[j], Ah, Bl);
                mma16816(s[j], Al, Bh);
            }
        }

        // ---- softmax on fragments ----
        float mxl = neg_inf_f(), mxh = neg_inf_f();
#pragma unroll
        for (int j = 0; j < 16; j++) {
            float b0 = (mrow[k0 + 8 * j + 2 * t]     != 0) ? 0.f : NEG_F;
            float b1 = (mrow[k0 + 8 * j + 2 * t + 1] != 0) ? 0.f : NEG_F;
            s[j][0] = fmaf(s[j][0], 0.125f, b0);
            s[j][1] = fmaf(s[j][1], 0.125f, b1);
            s[j][2] = fmaf(s[j][2], 0.125f, b0);
            s[j][3] = fmaf(s[j][3], 0.125f, b1);
            mxl = fmaxf(mxl, fmaxf(s[j][0], s[j][1]));
            mxh = fmaxf(mxh, fmaxf(s[j][2], s[j][3]));
        }
        mxl = fmaxf(mxl, __shfl_xor_sync(0xffffffffu, mxl, 1));
        mxl = fmaxf(mxl, __shfl_xor_sync(0xffffffffu, mxl, 2));
        mxh = fmaxf(mxh, __shfl_xor_sync(0xffffffffu, mxh, 1));
        mxh = fmaxf(mxh, __shfl_xor_sync(0xffffffffu, mxh, 2));
        float mnl = fmaxf(mpl, mxl);
        float mnh = fmaxf(mph, mxh);
        float sfl = __expf(mpl - mnl);
        float sfh = __expf(mph - mnh);
        float rsl = 0.f, rsh = 0.f;
#pragma unroll
        for (int j = 0; j < 16; j++) {
            s[j][0] = __expf(s[j][0] - mnl); rsl += s[j][0];
            s[j][1] = __expf(s[j][1] - mnl); rsl += s[j][1];
            s[j][2] = __expf(s[j][2] - mnh); rsh += s[j][2];
            s[j][3] = __expf(s[j][3] - mnh); rsh += s[j][3];
        }
        rsl += __shfl_xor_sync(0xffffffffu, rsl, 1);
        rsl += __shfl_xor_sync(0xffffffffu, rsl, 2);
        rsh += __shfl_xor_sync(0xffffffffu, rsh, 1);
        rsh += __shfl_xor_sync(0xffffffffu, rsh, 2);
        lsl = lsl * sfl + rsl;
        lsh = lsh * sfh + rsh;
        mpl = mnl;
        mph = mnh;

        // ---- O = O*sf + P V (P in registers, split on the fly) ----
#pragma unroll
        for (int f = 0; f < 8; f++) {
            acc[f][0] *= sfl; acc[f][1] *= sfl;
            acc[f][2] *= sfh; acc[f][3] *= sfh;
        }
#pragma unroll
        for (int ks = 0; ks < 8; ks++) {
            const int kb = ks * 16 + 2 * t;
            const int j0 = 2 * ks, j1 = 2 * ks + 1;
            uint32_t Ah[4], Al[4];
            splitpack(s[j0][0], s[j0][1], Ah[0], Al[0]);
            splitpack(s[j0][2], s[j0][3], Ah[1], Al[1]);
            splitpack(s[j1][0], s[j1][1], Ah[2], Al[2]);
            splitpack(s[j1][2], s[j1][3], Ah[3], Al[3]);
#pragma unroll
            for (int f = 0; f < 8; f++) {
                const int vr = 8 * f + g;
                uint32_t Bh[2], Bl[2];
                Bh[0] = *(const uint32_t*)&VhT[vr * 136 + kb];
                Bh[1] = *(const uint32_t*)&VhT[vr * 136 + kb + 8];
                Bl[0] = *(const uint32_t*)&VlT[vr * 136 + kb];
                Bl[1] = *(const uint32_t*)&VlT[vr * 136 + kb + 8];
                mma16816(acc[f], Ah, Bh);
                mma16816(acc[f], Ah, Bl);
                mma16816(acc[f], Al, Bh);
            }
        }
    }

    const float invl = 1.0f / lsl;
    const float invh = 1.0f / lsh;
    float* orow_lo = out + ((size_t)(b * SEQ + q0 + rlo)) * HID + h * HDIM;
    float* orow_hi = out + ((size_t)(b * SEQ + q0 + rhi)) * HID + h * HDIM;
#pragma unroll
    for (int f = 0; f < 8; f++) {
        int c = 8 * f + 2 * t;
        *(float2*)(orow_lo + c) = make_float2(acc[f][0] * invl, acc[f][1] * invl);
        *(float2*)(orow_hi + c) = make_float2(acc[f][2] * invh, acc[f][3] * invh);
    }
}

extern "C" void kernel_launch(void* const* d_in, const int* in_sizes, int n_in,
                              void* d_out, int out_size) {
    const float* X    = (const float*)d_in[0];
    const int*   mask = (const int*)d_in[1];
    const float* Wq   = (const float*)d_in[2];
    const float* Bq   = (const float*)d_in[3];
    const float* Wk   = (const float*)d_in[4];
    const float* Bk   = (const float*)d_in[5];
    const float* Wv   = (const float*)d_in[6];
    const float* Bv   = (const float*)d_in[7];
    float* out = (float*)d_out;

    split_x_kernel<<<MTOT * HID / 8 / 256, 256>>>(X);
    split_wt_kernel<<<dim3(HID / 32, HID / 32, 3), 256>>>(Wq, Wk, Wv);
    proj_kernel<<<dim3(HID / 128, MTOT / 128, 3), 256>>>(Bq, Bk, Bv);

    static const int smem_bytes = 108544;
    cudaFuncSetAttribute(attn_kernel,
                         cudaFuncAttributeMaxDynamicSharedMemorySize, smem_bytes);
    dim3 g2(SEQ / 128, BATCH * NHEAD);
    attn_kernel<<<g2, 256, smem_bytes>>>(mask, out);
}

// round 16
// speedup vs baseline: 2.8244x; 1.2088x over previous
#include <cuda_runtime.h>
#include <cuda_bf16.h>
#include <cstdint>

#define BATCH 4
#define SEQ   2048
#define NHEAD 16
#define HDIM  64
#define HID   1024
#define NEG_F (-3.4028234663852886e38f)

#define NELT (BATCH * NHEAD * SEQ * HDIM)
#define MTOT (BATCH * SEQ)              // 8192 rows

// Scratch: Q/K bf16 hi/lo in [bh][s][d]; V bf16 hi/lo TRANSPOSED [bh][d][s].
__device__ __nv_bfloat16 g_qh[NELT];
__device__ __nv_bfloat16 g_ql[NELT];
__device__ __nv_bfloat16 g_kh[NELT];
__device__ __nv_bfloat16 g_kl[NELT];
__device__ __nv_bfloat16 g_vh[NELT];
__device__ __nv_bfloat16 g_vl[NELT];
// Pre-split X (hi/lo) and pre-split+transposed Wq/Wk/Wv ([n][k], z-major).
__device__ __nv_bfloat16 g_xh[MTOT * HID];
__device__ __nv_bfloat16 g_xl[MTOT * HID];
__device__ __nv_bfloat16 g_wth[3 * HID * HID];
__device__ __nv_bfloat16 g_wtl[3 * HID * HID];

__device__ __forceinline__ float neg_inf_f() { return __int_as_float(0xff800000); }

__device__ __forceinline__ void mma16816(float* d, const uint32_t* a, const uint32_t* b) {
    asm volatile(
        "mma.sync.aligned.m16n8k16.row.col.f32.bf16.bf16.f32 "
        "{%0,%1,%2,%3}, {%4,%5,%6,%7}, {%8,%9}, {%0,%1,%2,%3};"
        : "+f"(d[0]), "+f"(d[1]), "+f"(d[2]), "+f"(d[3])
        : "r"(a[0]), "r"(a[1]), "r"(a[2]), "r"(a[3]), "r"(b[0]), "r"(b[1]));
}

__device__ __forceinline__ void ldsm_x4(uint32_t* r, uint32_t saddr) {
    asm volatile(
        "ldmatrix.sync.aligned.m8n8.x4.shared.b16 {%0,%1,%2,%3}, [%4];"
        : "=r"(r[0]), "=r"(r[1]), "=r"(r[2]), "=r"(r[3]) : "r"(saddr));
}

__device__ __forceinline__ void split2(float f, uint16_t& h, uint16_t& l) {
    __nv_bfloat16 hb = __float2bfloat16(f);
    __nv_bfloat16 lb = __float2bfloat16(f - __bfloat162float(hb));
    h = __bfloat16_as_ushort(hb);
    l = __bfloat16_as_ushort(lb);
}

// Split a float pair into packed bf16 hi-pair and lo-pair (f0 -> low half).
__device__ __forceinline__ void splitpack(float f0, float f1, uint32_t& ph, uint32_t& pl) {
    __nv_bfloat162 hp = __floats2bfloat162_rn(f0, f1);
    uint32_t p = *(uint32_t*)&hp;
    ph = p;
    float h0 = __uint_as_float(p << 16);
    float h1 = __uint_as_float(p & 0xFFFF0000u);
    __nv_bfloat162 lp = __floats2bfloat162_rn(f0 - h0, f1 - h1);
    pl = *(uint32_t*)&lp;
}

// ---------------------------------------------------------------------------
// split_x: X fp32 -> g_xh/g_xl bf16.
// ---------------------------------------------------------------------------
__global__ __launch_bounds__(256) void split_x_kernel(const float* __restrict__ X) {
    int idx = blockIdx.x * 256 + threadIdx.x;     // 0 .. MTOT*HID/8 - 1
    const float4* xp = (const float4*)X;
    float4 a = xp[idx * 2];
    float4 c = xp[idx * 2 + 1];
    const float f[8] = {a.x, a.y, a.z, a.w, c.x, c.y, c.z, c.w};
    uint4 uh, ul;
    uint32_t* ph = (uint32_t*)&uh;
    uint32_t* pl = (uint32_t*)&ul;
#pragma unroll
    for (int j = 0; j < 4; j++)
        splitpack(f[2 * j], f[2 * j + 1], ph[j], pl[j]);
    *(uint4*)(g_xh + (size_t)idx * 8) = uh;
    *(uint4*)(g_xl + (size_t)idx * 8) = ul;
}

// ---------------------------------------------------------------------------
// split_wt: W[k][n] fp32 -> transposed bf16 hi/lo [n][k]. 32x32 smem tiles.
// ---------------------------------------------------------------------------
__global__ __launch_bounds__(256) void split_wt_kernel(
    const float* __restrict__ Wq, const float* __restrict__ Wk,
    const float* __restrict__ Wv)
{
    __shared__ uint16_t shh[32 * 33];
    __shared__ uint16_t shl[32 * 33];
    const float* W = (blockIdx.z == 0) ? Wq : (blockIdx.z == 1) ? Wk : Wv;
    const size_t zoff = (size_t)blockIdx.z * HID * HID;
    const int k0 = blockIdx.y * 32;
    const int n0 = blockIdx.x * 32;
    const int tid = threadIdx.x;

#pragma unroll
    for (int p = 0; p < 4; p++) {
        int idx = tid + p * 256;
        int kl = idx >> 5;
        int nl = idx & 31;
        float f = W[(size_t)(k0 + kl) * HID + n0 + nl];
        uint16_t h, l;
        split2(f, h, l);
        shh[nl * 33 + kl] = h;
        shl[nl * 33 + kl] = l;
    }
    __syncthreads();
#pragma unroll
    for (int p = 0; p < 2; p++) {
        int idx = tid + p * 256;
        int nl = idx >> 4;
        int kp = idx & 15;
        uint32_t vh = ((uint32_t)shh[nl * 33 + kp * 2 + 1] << 16) | shh[nl * 33 + kp * 2];
        uint32_t vl = ((uint32_t)shl[nl * 33 + kp * 2 + 1] << 16) | shl[nl * 33 + kp * 2];
        size_t off = zoff + (size_t)(n0 + nl) * HID + k0 + kp * 2;
        *(uint32_t*)(g_wth + off) = vh;
        *(uint32_t*)(g_wtl + off) = vl;
    }
}

// ---------------------------------------------------------------------------
// proj_kernel: Q/K/V projections via bf16x3-split mma, ldmatrix fragment loads.
// BM=128, BN=128, BK=32. 8 warps (2m x 4n), warp 64x32, 4x4 m16n8k16 frags.
// Smem rows 40 bf16 (80B stride; ldmatrix bank-walk 20r mod 32 conflict-free).
// ---------------------------------------------------------------------------
__global__ __launch_bounds__(256) void proj_kernel(
    const float* __restrict__ Bq, const float* __restrict__ Bk,
    const float* __restrict__ Bv)
{
    __shared__ __nv_bfloat16 Xhs[128 * 40];
    __shared__ __nv_bfloat16 Xls[128 * 40];
    __shared__ __nv_bfloat16 Whs[128 * 40];
    __shared__ __nv_bfloat16 Wls[128 * 40];

    const int z = blockIdx.z;
    const float* __restrict__ Bi = (z == 0) ? Bq : (z == 1) ? Bk : Bv;
    const __nv_bfloat16* Wth = g_wth + (size_t)z * HID * HID;
    const __nv_bfloat16* Wtl = g_wtl + (size_t)z * HID * HID;

    const int tid  = threadIdx.x;
    const int warp = tid >> 5;
    const int lane = tid & 31;
    const int g    = lane >> 2;
    const int t    = lane & 3;
    const int wm   = (warp >> 2) * 64;
    const int wn   = (warp & 3) * 32;
    const int m0   = blockIdx.y * 128;
    const int n0   = blockIdx.x * 128;

    const int m4 = lane >> 3;    // ldmatrix matrix id
    const int r8 = lane & 7;     // row within matrix
    const uint32_t xh_b = (uint32_t)__cvta_generic_to_shared(Xhs);
    const uint32_t xl_b = (uint32_t)__cvta_generic_to_shared(Xls);
    const uint32_t wh_b = (uint32_t)__cvta_generic_to_shared(Whs);
    const uint32_t wl_b = (uint32_t)__cvta_generic_to_shared(Wls);
    // A: mats = (row-half = m4&1, k-half = m4>>1); B: mats = (col-half = m4>>1, k-half = m4&1)
    const uint32_t aoff = (uint32_t)((8 * (m4 & 1) + r8) * 80 + (m4 >> 1) * 16);
    const uint32_t boff = (uint32_t)((8 * (m4 >> 1) + r8) * 80 + (m4 & 1) * 16);

    float D[4][4][4];
#pragma unroll
    for (int fi = 0; fi < 4; fi++)
#pragma unroll
        for (int fj = 0; fj < 4; fj++)
#pragma unroll
            for (int e = 0; e < 4; e++) D[fi][fj][e] = 0.f;

    for (int k0 = 0; k0 < HID; k0 += 32) {
#pragma unroll
        for (int p = 0; p < 2; p++) {
            int idx = tid + p * 256;
            int row = idx >> 2;
            int seg = idx & 3;
            size_t xs = (size_t)(m0 + row) * HID + k0 + seg * 8;
            *(uint4*)&Xhs[row * 40 + seg * 8] = *(const uint4*)(g_xh + xs);
            *(uint4*)&Xls[row * 40 + seg * 8] = *(const uint4*)(g_xl + xs);
            size_t ws = (size_t)(n0 + row) * HID + k0 + seg * 8;
            *(uint4*)&Whs[row * 40 + seg * 8] = *(const uint4*)(Wth + ws);
            *(uint4*)&Wls[row * 40 + seg * 8] = *(const uint4*)(Wtl + ws);
        }
        __syncthreads();

#pragma unroll
        for (int ks = 0; ks < 2; ks++) {
            uint32_t Ah[4][4], Al[4][4];
#pragma unroll
            for (int fi = 0; fi < 4; fi++) {
                uint32_t base = (uint32_t)((wm + fi * 16) * 80 + ks * 32);
                ldsm_x4(Ah[fi], xh_b + base + aoff);
                ldsm_x4(Al[fi], xl_b + base + aoff);
            }
#pragma unroll
            for (int fj2 = 0; fj2 < 2; fj2++) {
                uint32_t Bh[4], Bl[4];
                uint32_t base = (uint32_t)((wn + fj2 * 16) * 80 + ks * 32);
                ldsm_x4(Bh, wh_b + base + boff);
                ldsm_x4(Bl, wl_b + base + boff);
#pragma unroll
                for (int fi = 0; fi < 4; fi++) {
                    mma16816(D[fi][2 * fj2],     Ah[fi], Bh + 0);
                    mma16816(D[fi][2 * fj2],     Ah[fi], Bl + 0);
                    mma16816(D[fi][2 * fj2],     Al[fi], Bh + 0);
                    mma16816(D[fi][2 * fj2 + 1], Ah[fi], Bh + 2);
                    mma16816(D[fi][2 * fj2 + 1], Ah[fi], Bl + 2);
                    mma16816(D[fi][2 * fj2 + 1], Al[fi], Bh + 2);
                }
            }
        }
        __syncthreads();
    }

    if (z < 2) {
        __nv_bfloat16* dh = (z == 0) ? g_qh : g_kh;
        __nv_bfloat16* dl = (z == 0) ? g_ql : g_kl;
#pragma unroll
        for (int fj = 0; fj < 4; fj++) {
            const int ncol = n0 + wn + fj * 8 + 2 * t;
            const int h    = ncol >> 6;
            const int d0c  = ncol & 63;
            const float b0 = Bi[ncol];
            const float b1 = Bi[ncol + 1];
#pragma unroll
            for (int fi = 0; fi < 4; fi++) {
#pragma unroll
                for (int half = 0; half < 2; half++) {
                    int m  = m0 + wm + fi * 16 + g + half * 8;
                    int bi = m >> 11;
                    int s  = m & (SEQ - 1);
                    size_t off = ((size_t)(bi * NHEAD + h) * SEQ + s) * HDIM + d0c;
                    uint32_t ph, pl;
                    splitpack(D[fi][fj][half * 2 + 0] + b0,
                              D[fi][fj][half * 2 + 1] + b1, ph, pl);
                    *(uint32_t*)(dh + off) = ph;
                    *(uint32_t*)(dl + off) = pl;
                }
            }
        }
    } else {
        // V: transposed [bh][d][s], scalar bf16 stores.
#pragma unroll
        for (int fj = 0; fj < 4; fj++) {
            const int ncol = n0 + wn + fj * 8 + 2 * t;
            const int h    = ncol >> 6;
            const int d0c  = ncol & 63;
            const float b0 = Bi[ncol];
            const float b1 = Bi[ncol + 1];
            const size_t dbase0 = ((size_t)h * HDIM + d0c) * SEQ;
            const size_t dbase1 = ((size_t)h * HDIM + d0c + 1) * SEQ;
#pragma unroll
            for (int fi = 0; fi < 4; fi++) {
#pragma unroll
                for (int half = 0; half < 2; half++) {
                    int m  = m0 + wm + fi * 16 + g + half * 8;
                    int bi = m >> 11;
                    int s  = m & (SEQ - 1);
                    size_t boff2 = (size_t)bi * NHEAD * HDIM * SEQ;
                    uint16_t h0, l0, h1, l1;
                    split2(D[fi][fj][half * 2 + 0] + b0, h0, l0);
                    split2(D[fi][fj][half * 2 + 1] + b1, h1, l1);
                    ((uint16_t*)g_vh)[boff2 + dbase0 + s] = h0;
                    ((uint16_t*)g_vl)[boff2 + dbase0 + s] = l0;
                    ((uint16_t*)g_vh)[boff2 + dbase1 + s] = h1;
                    ((uint16_t*)g_vl)[boff2 + dbase1 + s] = l1;
                }
            }
        }
    }
}

// ---------------------------------------------------------------------------
// Kernel 2: flash attention, BQ=128 x BK=128, 256 threads, 2 CTAs/SM.
// S and PV both bf16x3-split mma. P in registers. All fragment loads via
// ldmatrix.x4 (strides 144B/272B -> conflict-free bank walks).
// Smem (dynamic, 108544 B -> 2 CTAs/SM):
//   Qh @0, Ql @18432  (bf16[128][72]);  Kh @36864, Kl @55296 (bf16[128][72])
//   VhT @73728, VlT @91136 (bf16[64][136], V^T [d][k])
// ---------------------------------------------------------------------------
__global__ __launch_bounds__(256, 2) void attn_kernel(
    const int* __restrict__ mask,
    float* __restrict__ out)
{
    extern __shared__ char smraw[];
    __nv_bfloat16* Qh  = (__nv_bfloat16*)smraw;
    __nv_bfloat16* Ql  = (__nv_bfloat16*)(smraw + 18432);
    __nv_bfloat16* Kh  = (__nv_bfloat16*)(smraw + 36864);
    __nv_bfloat16* Kl  = (__nv_bfloat16*)(smraw + 55296);
    __nv_bfloat16* VhT = (__nv_bfloat16*)(smraw + 73728);
    __nv_bfloat16* VlT = (__nv_bfloat16*)(smraw + 91136);

    const int tid  = threadIdx.x;
    const int warp = tid >> 5;
    const int lane = tid & 31;
    const int g    = lane >> 2;
    const int t    = lane & 3;
    const int rlo  = warp * 16 + g;
    const int rhi  = rlo + 8;

    const int q0 = blockIdx.x * 128;
    const int bh = blockIdx.y;
    const int b  = bh >> 4;
    const int h  = bh & 15;

    const __nv_bfloat16* Qgh = g_qh + (size_t)bh * SEQ * HDIM;
    const __nv_bfloat16* Qgl = g_ql + (size_t)bh * SEQ * HDIM;
    const __nv_bfloat16* Kgh = g_kh + (size_t)bh * SEQ * HDIM;
    const __nv_bfloat16* Kgl = g_kl + (size_t)bh * SEQ * HDIM;
    const __nv_bfloat16* Vgh = g_vh + (size_t)bh * SEQ * HDIM;   // [d][s]
    const __nv_bfloat16* Vgl = g_vl + (size_t)bh * SEQ * HDIM;
    const int* __restrict__ mrow = mask + (size_t)b * SEQ;

    // ldmatrix per-lane address components.
    const int m4 = lane >> 3;
    const int r8 = lane & 7;
    const uint32_t smem_u32 = (uint32_t)__cvta_generic_to_shared(smraw);
    const uint32_t qh_b = smem_u32;
    const uint32_t ql_b = smem_u32 + 18432;
    const uint32_t kh_b = smem_u32 + 36864;
    const uint32_t kl_b = smem_u32 + 55296;
    const uint32_t vh_b = smem_u32 + 73728;
    const uint32_t vl_b = smem_u32 + 91136;
    // Q (A-frag): mats (row-half = m4&1, k-half = m4>>1); row stride 144B.
    const uint32_t qoff = (uint32_t)(warp * 2304 + (8 * (m4 & 1) + r8) * 144 + (m4 >> 1) * 16);
    // K (B-frag): mats (j-half = m4>>1, k-half = m4&1).
    const uint32_t koff = (uint32_t)((8 * (m4 >> 1) + r8) * 144 + (m4 & 1) * 16);
    // V (B-frag): row stride 272B.
    const uint32_t voff = (uint32_t)((8 * (m4 >> 1) + r8) * 272 + (m4 & 1) * 16);

#pragma unroll
    for (int p = 0; p < 4; p++) {
        int idx = tid + p * 256;
        int row = idx >> 3;
        int seg = idx & 7;
        uint4 vh = *(const uint4*)(Qgh + (size_t)(q0 + row) * HDIM + seg * 8);
        uint4 vl = *(const uint4*)(Qgl + (size_t)(q0 + row) * HDIM + seg * 8);
        *(uint4*)&Qh[row * 72 + seg * 8] = vh;
        *(uint4*)&Ql[row * 72 + seg * 8] = vl;
    }

    float acc[8][4];
#pragma unroll
    for (int f = 0; f < 8; f++)
#pragma unroll
        for (int e = 0; e < 4; e++) acc[f][e] = 0.f;
    float mpl = neg_inf_f(), mph = neg_inf_f();
    float lsl = 0.f, lsh = 0.f;

    for (int kt = 0; kt < SEQ / 128; kt++) {
        const int k0 = kt * 128;
        __syncthreads();   // prev tile's K/V smem reads done; (iter 0) Q visible

#pragma unroll
        for (int p = 0; p < 4; p++) {
            int idx = tid + p * 256;
            int row = idx >> 3;
            int seg = idx & 7;
            uint4 vh = *(const uint4*)(Kgh + (size_t)(k0 + row) * HDIM + seg * 8);
            uint4 vl = *(const uint4*)(Kgl + (size_t)(k0 + row) * HDIM + seg * 8);
            *(uint4*)&Kh[row * 72 + seg * 8] = vh;
            *(uint4*)&Kl[row * 72 + seg * 8] = vl;
        }
#pragma unroll
        for (int p = 0; p < 4; p++) {
            int idx = tid + p * 256;
            int row = idx >> 4;
            int seg = idx & 15;
            uint4 vh = *(const uint4*)(Vgh + (size_t)row * SEQ + k0 + seg * 8);
            uint4 vl = *(const uint4*)(Vgl + (size_t)row * SEQ + k0 + seg * 8);
            *(uint4*)&VhT[row * 136 + seg * 8] = vh;
            *(uint4*)&VlT[row * 136 + seg * 8] = vl;
        }
        __syncthreads();

        // ---- S = Q K^T (3-term split mma, ldmatrix loads) ----
        float s[16][4];
#pragma unroll
        for (int j = 0; j < 16; j++)
#pragma unroll
            for (int e = 0; e < 4; e++) s[j][e] = 0.f;

#pragma unroll
        for (int ks = 0; ks < 4; ks++) {
            uint32_t Ah[4], Al[4];
            ldsm_x4(Ah, qh_b + qoff + ks * 32);
            ldsm_x4(Al, ql_b + qoff + ks * 32);
#pragma unroll
            for (int j2 = 0; j2 < 8; j2++) {
                uint32_t Bh[4], Bl[4];
                ldsm_x4(Bh, kh_b + koff + j2 * 2304 + ks * 32);
                ldsm_x4(Bl, kl_b + koff + j2 * 2304 + ks * 32);
                mma16816(s[2 * j2],     Ah, Bh + 0);
                mma16816(s[2 * j2],     Ah, Bl + 0);
                mma16816(s[2 * j2],     Al, Bh + 0);
                mma16816(s[2 * j2 + 1], Ah, Bh + 2);
                mma16816(s[2 * j2 + 1], Ah, Bl + 2);
                mma16816(s[2 * j2 + 1], Al, Bh + 2);
            }
        }

        // ---- softmax on fragments ----
        float mxl = neg_inf_f(), mxh = neg_inf_f();
#pragma unroll
        for (int j = 0; j < 16; j++) {
            float b0 = (mrow[k0 + 8 * j + 2 * t]     != 0) ? 0.f : NEG_F;
            float b1 = (mrow[k0 + 8 * j + 2 * t + 1] != 0) ? 0.f : NEG_F;
            s[j][0] = fmaf(s[j][0], 0.125f, b0);
            s[j][1] = fmaf(s[j][1], 0.125f, b1);
            s[j][2] = fmaf(s[j][2], 0.125f, b0);
            s[j][3] = fmaf(s[j][3], 0.125f, b1);
            mxl = fmaxf(mxl, fmaxf(s[j][0], s[j][1]));
            mxh = fmaxf(mxh, fmaxf(s[j][2], s[j][3]));
        }
        mxl = fmaxf(mxl, __shfl_xor_sync(0xffffffffu, mxl, 1));
        mxl = fmaxf(mxl, __shfl_xor_sync(0xffffffffu, mxl, 2));
        mxh = fmaxf(mxh, __shfl_xor_sync(0xffffffffu, mxh, 1));
        mxh = fmaxf(mxh, __shfl_xor_sync(0xffffffffu, mxh, 2));
        float mnl = fmaxf(mpl, mxl);
        float mnh = fmaxf(mph, mxh);
        float sfl = __expf(mpl - mnl);
        float sfh = __expf(mph - mnh);
        float rsl = 0.f, rsh = 0.f;
#pragma unroll
        for (int j = 0; j < 16; j++) {
            s[j][0] = __expf(s[j][0] - mnl); rsl += s[j][0];
            s[j][1] = __expf(s[j][1] - mnl); rsl += s[j][1];
            s[j][2] = __expf(s[j][2] - mnh); rsh += s[j][2];
            s[j][3] = __expf(s[j][3] - mnh); rsh += s[j][3];
        }
        rsl += __shfl_xor_sync(0xffffffffu, rsl, 1);
        rsl += __shfl_xor_sync(0xffffffffu, rsl, 2);
        rsh += __shfl_xor_sync(0xffffffffu, rsh, 1);
        rsh += __shfl_xor_sync(0xffffffffu, rsh, 2);
        lsl = lsl * sfl + rsl;
        lsh = lsh * sfh + rsh;
        mpl = mnl;
        mph = mnh;

        // ---- O = O*sf + P V (P in registers, split on the fly) ----
#pragma unroll
        for (int f = 0; f < 8; f++) {
            acc[f][0] *= sfl; acc[f][1] *= sfl;
            acc[f][2] *= sfh; acc[f][3] *= sfh;
        }
#pragma unroll
        for (int ks = 0; ks < 8; ks++) {
            const int j0 = 2 * ks, j1 = 2 * ks + 1;
            uint32_t Ah[4], Al[4];
            splitpack(s[j0][0], s[j0][1], Ah[0], Al[0]);
            splitpack(s[j0][2], s[j0][3], Ah[1], Al[1]);
            splitpack(s[j1][0], s[j1][1], Ah[2], Al[2]);
            splitpack(s[j1][2], s[j1][3], Ah[3], Al[3]);
#pragma unroll
            for (int f2 = 0; f2 < 4; f2++) {
                uint32_t Bh[4], Bl[4];
                ldsm_x4(Bh, vh_b + voff + f2 * 4352 + ks * 32);
                ldsm_x4(Bl, vl_b + voff + f2 * 4352 + ks * 32);
                mma16816(acc[2 * f2],     Ah, Bh + 0);
                mma16816(acc[2 * f2],     Ah, Bl + 0);
                mma16816(acc[2 * f2],     Al, Bh + 0);
                mma16816(acc[2 * f2 + 1], Ah, Bh + 2);
                mma16816(acc[2 * f2 + 1], Ah, Bl + 2);
                mma16816(acc[2 * f2 + 1], Al, Bh + 2);
            }
        }
    }

    const float invl = 1.0f / lsl;
    const float invh = 1.0f / lsh;
    float* orow_lo = out + ((size_t)(b * SEQ + q0 + rlo)) * HID + h * HDIM;
    float* orow_hi = out + ((size_t)(b * SEQ + q0 + rhi)) * HID + h * HDIM;
#pragma unroll
    for (int f = 0; f < 8; f++) {
        int c = 8 * f + 2 * t;
        *(float2*)(orow_lo + c) = make_float2(acc[f][0] * invl, acc[f][1] * invl);
        *(float2*)(orow_hi + c) = make_float2(acc[f][2] * invh, acc[f][3] * invh);
    }
}

extern "C" void kernel_launch(void* const* d_in, const int* in_sizes, int n_in,
                              void* d_out, int out_size) {
    const float* X    = (const float*)d_in[0];
    const int*   mask = (const int*)d_in[1];
    const float* Wq   = (const float*)d_in[2];
    const float* Bq   = (const float*)d_in[3];
    const float* Wk   = (const float*)d_in[4];
    const float* Bk   = (const float*)d_in[5];
    const float* Wv   = (const float*)d_in[6];
    const float* Bv   = (const float*)d_in[7];
    float* out = (float*)d_out;

    split_x_kernel<<<MTOT * HID / 8 / 256, 256>>>(X);
    split_wt_kernel<<<dim3(HID / 32, HID / 32, 3), 256>>>(Wq, Wk, Wv);
    proj_kernel<<<dim3(HID / 128, MTOT / 128, 3), 256>>>(Bq, Bk, Bv);

    static const int smem_bytes = 108544;
    cudaFuncSetAttribute(attn_kernel,
                         cudaFuncAttributeMaxDynamicSharedMemorySize, smem_bytes);
    dim3 g2(SEQ / 128, BATCH * NHEAD);
    attn_kernel<<<g2, 256, smem_bytes>>>(mask, out);
}